// round 6
// baseline (speedup 1.0000x reference)
#include <cuda_runtime.h>
#include <cstdint>
#include <cstddef>

#define DIMC 192
#define ROWSTRIDE 576            /* 3*DIMC */
#define NB   8
#define NTOK 4096
#define BR   128
#define BC   32
#define NTILES (NTOK / BC)
#define NTHREADS 512
#define LDQ 208                  /* permuted Q row stride  */
#define LDK 196                  /* raw K row stride       */
#define LDV 200                  /* raw V row stride       */
#define LDP 36                   /* permuted P row stride  */
#define NEG_SCALE_LOG2E (-0.104117549f)   /* -(192^-0.5)*log2(e) */

// ---- smem layout (floats) ----
#define SQ_OFF   0
#define SQ_SZ    (BR * LDQ)               /* 26624 */
#define SK_OFF   (SQ_OFF + SQ_SZ)
#define SK_SZ    (BC * LDK)               /* 6272  */
#define SV_OFF   (SK_OFF + 2 * SK_SZ)
#define SV_SZ    (BC * LDV)               /* 6400  */
#define SP_OFF   (SV_OFF + 2 * SV_SZ)
#define SP_SZ    (BR * LDP)               /* 4608  */
#define SK2_OFF  (SP_OFF + SP_SZ)         /* 32 (+pad) */
#define SQ2_OFF  (SK2_OFF + 64)           /* 128   */
#define SL_OFF   (SQ2_OFF + 128)          /* 256   */
#define SMEM_FLOATS (SL_OFF + 256)
#define SMEM_BYTES  (SMEM_FLOATS * 4)     /* 228096 */

__device__ __forceinline__ uint32_t fu(float f) { return __float_as_uint(f); }
__device__ __forceinline__ float maskf(float x) {
    return __uint_as_float(__float_as_uint(x) & 0xFFFFE000u);   /* tf32 truncation */
}
__device__ __forceinline__ float f2tff(float f) {              /* tf32 round-to-nearest */
    uint32_t u; asm("cvt.rna.tf32.f32 %0, %1;" : "=r"(u) : "f"(f));
    return __uint_as_float(u);
}
__device__ __forceinline__ float sqrt_approx(float x) {
    float r; asm("sqrt.approx.f32 %0, %1;" : "=f"(r) : "f"(x)); return r;
}
__device__ __forceinline__ float ex2_approx(float x) {
    float r; asm("ex2.approx.f32 %0, %1;" : "=f"(r) : "f"(x)); return r;
}
__device__ __forceinline__ uint32_t smem_u32(const void* p) {
    uint32_t a;
    asm("{ .reg .u64 t; cvta.to.shared.u64 t, %1; cvt.u32.u64 %0, t; }" : "=r"(a) : "l"(p));
    return a;
}

#define CP_ASYNC16(dst, src) \
    asm volatile("cp.async.cg.shared.global [%0], [%1], 16;" :: "r"(dst), "l"(src) : "memory")
#define CP_COMMIT() asm volatile("cp.async.commit_group;" ::: "memory")
#define CP_WAIT0()  asm volatile("cp.async.wait_group 0;" ::: "memory")

__device__ __forceinline__ void mma8(float* c,
        uint32_t a0, uint32_t a1, uint32_t a2, uint32_t a3,
        uint32_t b0, uint32_t b1) {
    asm volatile("mma.sync.aligned.m16n8k8.row.col.f32.tf32.tf32.f32 "
        "{%0,%1,%2,%3}, {%4,%5,%6,%7}, {%8,%9}, {%0,%1,%2,%3};"
        : "+f"(c[0]), "+f"(c[1]), "+f"(c[2]), "+f"(c[3])
        : "r"(a0), "r"(a1), "r"(a2), "r"(a3), "r"(b0), "r"(b1));
}

// prefetch raw K/V for tile st into buffer (st & 1): 6 LDGSTS per thread
__device__ __forceinline__ void prefetch_kv(uint32_t smb, const float* __restrict__ qkv,
                                            int b, int st) {
    const int tid = threadIdx.x;
    const int buf = st & 1;
    const float* base = qkv + ((size_t)(b * NTOK + st * BC)) * ROWSTRIDE + DIMC;
    const uint32_t kd = smb + (SK_OFF + buf * SK_SZ) * 4;
    const uint32_t vd = smb + (SV_OFF + buf * SV_SZ) * 4;
    #pragma unroll
    for (int i = 0; i < 3; i++) {
        int idx = tid + i * NTHREADS;      // 0..1535 = 32 rows x 48 float4
        int r = idx / 48, c = (idx - r * 48) * 4;
        CP_ASYNC16(kd + (uint32_t)(r * LDK + c) * 4, base + (size_t)r * ROWSTRIDE + c);
    }
    #pragma unroll
    for (int i = 0; i < 3; i++) {
        int idx = tid + i * NTHREADS;
        int r = idx / 48, c = (idx - r * 48) * 4;
        CP_ASYNC16(vd + (uint32_t)(r * LDV + c) * 4, base + (size_t)r * ROWSTRIDE + DIMC + c);
    }
}

__global__ void __launch_bounds__(NTHREADS, 1)
qkv_l2attn_kernel(const float* __restrict__ qkv, float* __restrict__ out)
{
    extern __shared__ float sm[];
    float* sQ  = sm + SQ_OFF;
    float* sP  = sm + SP_OFF;
    float* sK2 = sm + SK2_OFF;
    float* sQ2 = sm + SQ2_OFF;
    float* sL  = sm + SL_OFF;
    const uint32_t smb = smem_u32(sm);

    const int tid  = threadIdx.x;
    const int warp = tid >> 5;
    const int lane = tid & 31;
    const int g    = lane >> 2;
    const int t4   = lane & 3;
    const int wr   = warp & 7;       // row-group: rows wr*16 .. +16
    const int wh   = warp >> 3;      // key-half (QK) / col-half (PV)
    const int R    = wr * 16;
    const int KB   = wh * 16;        // key base within tile
    const int CB   = wh * 96;        // output column base

    const int b  = blockIdx.y;
    const int q0 = blockIdx.x * BR;

    // ---- prologue: start tile-0 prefetch, then Q -> permuted smem ----
    prefetch_kv(smb, qkv, b, 0);
    CP_COMMIT();

    const float* qptr = qkv + ((size_t)(b * NTOK + q0)) * ROWSTRIDE;
    #pragma unroll
    for (int it = 0; it < 12; it++) {
        int idx = tid * 4 + it * (NTHREADS * 4);
        int r = idx / DIMC, c = idx - r * DIMC;       // c % 4 == 0
        float4 v = *(const float4*)(qptr + (size_t)r * ROWSTRIDE + c);
        int base = (c >> 3) * 2 + ((c >> 2) & 1);     // position within t4-block
        float* row = sQ + r * LDQ + base;
        row[0]       = v.x;
        row[52]      = v.y;
        row[104]     = v.z;
        row[156]     = v.w;
    }
    __syncthreads();
    {   // q2 from masked values: 4 threads per row (one t4-block each)
        int r = tid >> 2, blk = tid & 3;
        const float* p = sQ + r * LDQ + blk * 52;
        float s = 0.f;
        #pragma unroll
        for (int i = 0; i < 12; i++) {
            float4 v = *(const float4*)(p + i * 4);
            float x0 = maskf(v.x), x1 = maskf(v.y), x2 = maskf(v.z), x3 = maskf(v.w);
            s += x0*x0 + x1*x1 + x2*x2 + x3*x3;
        }
        s += __shfl_xor_sync(0xffffffffu, s, 1);
        s += __shfl_xor_sync(0xffffffffu, s, 2);
        if (blk == 0) sQ2[r] = s;
    }
    __syncthreads();

    const float q2a = sQ2[R + g];
    const float q2b = sQ2[R + 8 + g];

    float l0 = 0.f, l1 = 0.f;
    float o[12][4];
    #pragma unroll
    for (int n = 0; n < 12; n++) { o[n][0]=0.f; o[n][1]=0.f; o[n][2]=0.f; o[n][3]=0.f; }

    for (int st = 0; st < NTILES; ++st) {
        const int buf = st & 1;
        float* sK = sm + SK_OFF + buf * SK_SZ;
        float* sV = sm + SV_OFF + buf * SV_SZ;

        CP_WAIT0();
        __syncthreads();                       // tile st visible; PV(st-1) done everywhere

        if (st + 1 < NTILES) { prefetch_kv(smb, qkv, b, st + 1); CP_COMMIT(); }

        {   // k2 for this tile: 16 threads per key row
            int r = tid >> 4, seg = tid & 15;
            const float* p = sK + r * LDK + seg * 12;
            float s = 0.f;
            #pragma unroll
            for (int i = 0; i < 3; i++) {
                float4 v = *(const float4*)(p + i * 4);
                float x0 = maskf(v.x), x1 = maskf(v.y), x2 = maskf(v.z), x3 = maskf(v.w);
                s += x0*x0 + x1*x1 + x2*x2 + x3*x3;
            }
            s += __shfl_xor_sync(0xffffffffu, s, 1);
            s += __shfl_xor_sync(0xffffffffu, s, 2);
            s += __shfl_xor_sync(0xffffffffu, s, 4);
            s += __shfl_xor_sync(0xffffffffu, s, 8);
            if (seg == 0) sK2[r] = s;
        }

        // ---- S = Q K^T (per warp: 16 rows x 16 keys) ----
        float sacc[2][4];
        sacc[0][0]=0.f; sacc[0][1]=0.f; sacc[0][2]=0.f; sacc[0][3]=0.f;
        sacc[1][0]=0.f; sacc[1][1]=0.f; sacc[1][2]=0.f; sacc[1][3]=0.f;

        const float* qlo = sQ + (R + g) * LDQ + t4 * 52;
        const float* qhi = sQ + (R + 8 + g) * LDQ + t4 * 52;
        #pragma unroll
        for (int j = 0; j < 12; j++) {
            float4 alo = *(const float4*)(qlo + j * 4);
            float4 ahi = *(const float4*)(qhi + j * 4);
            #pragma unroll
            for (int h = 0; h < 2; h++) {
                uint32_t a0 = fu(h ? alo.z : alo.x);
                uint32_t a1 = fu(h ? ahi.z : ahi.x);
                uint32_t a2 = fu(h ? alo.w : alo.y);
                uint32_t a3 = fu(h ? ahi.w : ahi.y);
                const int kk = (2 * j + h) * 8;
                #pragma unroll
                for (int n = 0; n < 2; n++) {
                    uint32_t b0 = fu(sK[(KB + n * 8 + g) * LDK + kk + t4]);
                    uint32_t b1 = fu(sK[(KB + n * 8 + g) * LDK + kk + 4 + t4]);
                    mma8(sacc[n], a0, a1, a2, a3, b0, b1);
                }
            }
        }
        __syncthreads();                       // k2 visible

        // ---- softmax + P store (permuted layout) ----
        #pragma unroll
        for (int n = 0; n < 2; n++) {
            int c0 = KB + n * 8 + 2 * t4;
            float2 k2v = *(const float2*)(sK2 + c0);
            float d00 = fmaxf(fmaf(sacc[n][0], -2.f, q2a + k2v.x), 0.f);
            float d01 = fmaxf(fmaf(sacc[n][1], -2.f, q2a + k2v.y), 0.f);
            float d10 = fmaxf(fmaf(sacc[n][2], -2.f, q2b + k2v.x), 0.f);
            float d11 = fmaxf(fmaf(sacc[n][3], -2.f, q2b + k2v.y), 0.f);
            float p00 = f2tff(ex2_approx(sqrt_approx(d00) * NEG_SCALE_LOG2E));
            float p01 = f2tff(ex2_approx(sqrt_approx(d01) * NEG_SCALE_LOG2E));
            float p10 = f2tff(ex2_approx(sqrt_approx(d10) * NEG_SCALE_LOG2E));
            float p11 = f2tff(ex2_approx(sqrt_approx(d11) * NEG_SCALE_LOG2E));
            l0 += p00 + p01; l1 += p10 + p11;
            int pos0 = ((2 * t4) & 3) * 8 + (wh * 2 + n) * 2 + (t4 >> 1);
            sP[(R + g)     * LDP + pos0    ] = p00;
            sP[(R + g)     * LDP + pos0 + 8] = p01;
            sP[(R + 8 + g) * LDP + pos0    ] = p10;
            sP[(R + 8 + g) * LDP + pos0 + 8] = p11;
        }
        __syncthreads();                       // full P visible

        // ---- O += P V (per warp: 16 rows x 96 cols) ----
        const float* plo = sP + (R + g) * LDP + t4 * 8;
        const float* phi = sP + (R + 8 + g) * LDP + t4 * 8;
        #pragma unroll
        for (int j = 0; j < 2; j++) {
            float4 alo = *(const float4*)(plo + j * 4);
            float4 ahi = *(const float4*)(phi + j * 4);
            #pragma unroll
            for (int h = 0; h < 2; h++) {
                uint32_t a0 = fu(h ? alo.z : alo.x);
                uint32_t a1 = fu(h ? ahi.z : ahi.x);
                uint32_t a2 = fu(h ? alo.w : alo.y);
                uint32_t a3 = fu(h ? ahi.w : ahi.y);
                const int kk = (2 * j + h) * 8;
                #pragma unroll
                for (int nn = 0; nn < 12; nn++) {
                    uint32_t b0 = fu(sV[(kk +     t4) * LDV + CB + nn * 8 + g]);
                    uint32_t b1 = fu(sV[(kk + 4 + t4) * LDV + CB + nn * 8 + g]);
                    mma8(o[nn], a0, a1, a2, a3, b0, b1);
                }
            }
        }
    }

    // ---- epilogue: merge l halves, normalize, write ----
    l0 += __shfl_xor_sync(0xffffffffu, l0, 1);
    l0 += __shfl_xor_sync(0xffffffffu, l0, 2);
    l1 += __shfl_xor_sync(0xffffffffu, l1, 1);
    l1 += __shfl_xor_sync(0xffffffffu, l1, 2);
    if (t4 == 0) {
        sL[wh * 128 + R + g]     = l0;
        sL[wh * 128 + R + 8 + g] = l1;
    }
    __syncthreads();
    float il0 = 1.f / (sL[R + g]     + sL[128 + R + g]);
    float il1 = 1.f / (sL[R + 8 + g] + sL[128 + R + 8 + g]);

    size_t orow0 = ((size_t)(b * NTOK + q0 + R + g)) * DIMC + CB;
    size_t orow1 = orow0 + (size_t)8 * DIMC;
    #pragma unroll
    for (int nn = 0; nn < 12; nn++) {
        int col = nn * 8 + 2 * t4;
        *(float2*)(out + orow0 + col) = make_float2(o[nn][0] * il0, o[nn][1] * il0);
        *(float2*)(out + orow1 + col) = make_float2(o[nn][2] * il1, o[nn][3] * il1);
    }
}

extern "C" void kernel_launch(void* const* d_in, const int* in_sizes, int n_in,
                              void* d_out, int out_size) {
    const float* qkv = (const float*)d_in[0];
    float* out = (float*)d_out;
    cudaFuncSetAttribute(qkv_l2attn_kernel,
                         cudaFuncAttributeMaxDynamicSharedMemorySize, SMEM_BYTES);
    dim3 grid(NTOK / BR, NB);
    qkv_l2attn_kernel<<<grid, NTHREADS, SMEM_BYTES>>>(qkv, out);
}

// round 8
// speedup vs baseline: 1.0854x; 1.0854x over previous
#include <cuda_runtime.h>
#include <cstdint>
#include <cstddef>

#define DIMC 192
#define ROWSTRIDE 576
#define NB   8
#define NTOK 4096
#define BR   128
#define BC   32
#define NTILES (NTOK / BC)
#define NTHREADS 256
#define LDQ  208     /* permuted Q stride */
#define LDK  196     /* raw K stride      */
#define LDVR 204     /* raw V stride      */
#define LDVT 36      /* V^T stride        */
#define NEG_SCALE_LOG2E (-0.104117549f)

// ---- smem layout (floats) ----
#define SQ_OFF   0
#define SQ_SZ    (BR * LDQ)              /* 26624 */
#define SK_OFF   (SQ_OFF + SQ_SZ)
#define SK_SZ    (BC * LDK)              /* 6272 x2 */
#define SVR_OFF  (SK_OFF + 2 * SK_SZ)
#define SVR_SZ   (BC * LDVR)             /* 6528 */
#define SVT_OFF  (SVR_OFF + SVR_SZ)
#define SVT_SZ   (DIMC * LDVT)           /* 6912 */
#define SK2_OFF  (SVT_OFF + SVT_SZ)      /* 32  */
#define SQ2_OFF  (SK2_OFF + 32)          /* 128 */
#define SMEM_FLOATS (SQ2_OFF + 128)
#define SMEM_BYTES  (SMEM_FLOATS * 4)    /* 211,072 */

__device__ __forceinline__ uint32_t fu(float f) { return __float_as_uint(f); }
__device__ __forceinline__ float maskf(float x) {
    return __uint_as_float(__float_as_uint(x) & 0xFFFFE000u);
}
__device__ __forceinline__ float sqrt_approx(float x) {
    float r; asm("sqrt.approx.f32 %0, %1;" : "=f"(r) : "f"(x)); return r;
}
__device__ __forceinline__ float ex2_approx(float x) {
    float r; asm("ex2.approx.f32 %0, %1;" : "=f"(r) : "f"(x)); return r;
}
__device__ __forceinline__ uint32_t smem_u32(const void* p) {
    uint32_t a;
    asm("{ .reg .u64 t; cvta.to.shared.u64 t, %1; cvt.u32.u64 %0, t; }" : "=r"(a) : "l"(p));
    return a;
}

#define CP_ASYNC16(dst, src) \
    asm volatile("cp.async.cg.shared.global [%0], [%1], 16;" :: "r"(dst), "l"(src) : "memory")
#define CP_COMMIT() asm volatile("cp.async.commit_group;" ::: "memory")
#define CP_WAIT0()  asm volatile("cp.async.wait_group 0;" ::: "memory")

__device__ __forceinline__ void mma8(float* c,
        uint32_t a0, uint32_t a1, uint32_t a2, uint32_t a3,
        uint32_t b0, uint32_t b1) {
    asm volatile("mma.sync.aligned.m16n8k8.row.col.f32.tf32.tf32.f32 "
        "{%0,%1,%2,%3}, {%4,%5,%6,%7}, {%8,%9}, {%0,%1,%2,%3};"
        : "+f"(c[0]), "+f"(c[1]), "+f"(c[2]), "+f"(c[3])
        : "r"(a0), "r"(a1), "r"(a2), "r"(a3), "r"(b0), "r"(b1));
}

__device__ __forceinline__ void ldsm_x4(uint32_t& r0, uint32_t& r1,
                                        uint32_t& r2, uint32_t& r3, uint32_t addr) {
    asm volatile("ldmatrix.sync.aligned.m8n8.x4.shared.b16 {%0,%1,%2,%3}, [%4];"
        : "=r"(r0), "=r"(r1), "=r"(r2), "=r"(r3) : "r"(addr));
}

// prefetch raw K/V for tile st (K double-buffered, raw V single)
// 32 rows x 48 float4 = 1536 per matrix -> 6 iterations of 256 threads
__device__ __forceinline__ void prefetch_kv(uint32_t smb, const float* __restrict__ qkv,
                                            int b, int st) {
    const int tid = threadIdx.x;
    const float* base = qkv + ((size_t)(b * NTOK + st * BC)) * ROWSTRIDE + DIMC;
    const uint32_t kd = smb + (SK_OFF + (st & 1) * SK_SZ) * 4;
    const uint32_t vd = smb + SVR_OFF * 4;
    #pragma unroll
    for (int i = 0; i < 6; i++) {
        int idx = tid + i * NTHREADS;
        int r = idx / 48, c = (idx - r * 48) * 4;
        CP_ASYNC16(kd + (uint32_t)(r * LDK + c) * 4, base + (size_t)r * ROWSTRIDE + c);
    }
    #pragma unroll
    for (int i = 0; i < 6; i++) {
        int idx = tid + i * NTHREADS;
        int r = idx / 48, c = (idx - r * 48) * 4;
        CP_ASYNC16(vd + (uint32_t)(r * LDVR + c) * 4, base + (size_t)r * ROWSTRIDE + DIMC + c);
    }
}

__global__ void __launch_bounds__(NTHREADS, 1)
qkv_l2attn_kernel(const float* __restrict__ qkv, float* __restrict__ out)
{
    extern __shared__ float sm[];
    float* sQ  = sm + SQ_OFF;
    float* sVR = sm + SVR_OFF;
    float* sVT = sm + SVT_OFF;
    float* sK2 = sm + SK2_OFF;
    float* sQ2 = sm + SQ2_OFF;
    const uint32_t smb = smem_u32(sm);

    const int tid  = threadIdx.x;
    const int warp = tid >> 5;
    const int lane = tid & 31;
    const int g    = lane >> 2;
    const int t4   = lane & 3;
    const int R    = warp * 16;

    const int b  = blockIdx.y;
    const int q0 = blockIdx.x * BR;

    // ---- prologue ----
    prefetch_kv(smb, qkv, b, 0);
    CP_COMMIT();

    // Q -> permuted smem (raw fp32)
    const float* qptr = qkv + ((size_t)(b * NTOK + q0)) * ROWSTRIDE;
    #pragma unroll
    for (int it = 0; it < 24; it++) {
        int idx = tid * 4 + it * (NTHREADS * 4);
        int r = idx / DIMC, c = idx - r * DIMC;
        float4 v = *(const float4*)(qptr + (size_t)r * ROWSTRIDE + c);
        int base = (c >> 3) * 2 + ((c >> 2) & 1);
        float* row = sQ + r * LDQ + base;
        row[0]   = v.x;
        row[52]  = v.y;
        row[104] = v.z;
        row[156] = v.w;
    }
    __syncthreads();
    {   // q2 (masked): 2 threads per row, 2 t4-blocks each
        int r = tid >> 1, hb = tid & 1;
        float s = 0.f;
        #pragma unroll
        for (int bb = 0; bb < 2; bb++) {
            const float* p = sQ + r * LDQ + (hb * 2 + bb) * 52;
            #pragma unroll
            for (int i = 0; i < 12; i++) {
                float4 v = *(const float4*)(p + i * 4);
                float x0 = maskf(v.x), x1 = maskf(v.y), x2 = maskf(v.z), x3 = maskf(v.w);
                s += x0*x0 + x1*x1 + x2*x2 + x3*x3;
            }
        }
        s += __shfl_xor_sync(0xffffffffu, s, 1);
        if (hb == 0) sQ2[r] = s;
    }
    __syncthreads();

    const float q2a = sQ2[R + g];
    const float q2b = sQ2[R + 8 + g];

    float l0 = 0.f, l1 = 0.f;
    float o[24][4];
    #pragma unroll
    for (int n = 0; n < 24; n++) { o[n][0]=0.f; o[n][1]=0.f; o[n][2]=0.f; o[n][3]=0.f; }

    const int src_lo = (lane & ~3) | (t4 >> 1);
    const int src_hi = src_lo + 2;
    const bool oddc  = (t4 & 1);

    // per-lane LDSM base addresses (bytes)
    const uint32_t lrow = ((lane >> 4) << 3) + (lane & 7);    // row within matrix pair
    const uint32_t hoff = ((lane >> 3) & 1) << 4;             // +16B for b1 half
    const uint32_t kBase0 = smb + SK_OFF * 4 + lrow * (LDK * 4) + hoff;
    const uint32_t vtBase = smb + SVT_OFF * 4 + lrow * (LDVT * 4) + hoff;
    const float* qlo = sQ + (R + g) * LDQ + t4 * 52;
    const float* qhi = qlo + 8 * LDQ;

    for (int st = 0; st < NTILES; ++st) {
        CP_WAIT0();
        __syncthreads();                 // K/rawV(st) visible; all PV(st-1) readers done

        {   // repack rawV -> VT (conflict-free STS: addr = c*36 + key)
            int r = tid & 31, seg = tid >> 5;
            const float* p = sVR + r * LDVR + seg * 24;
            #pragma unroll
            for (int i = 0; i < 6; i++) {
                float4 v = *(const float4*)(p + i * 4);
                int c = seg * 24 + i * 4;
                sVT[(c + 0) * LDVT + r] = v.x;
                sVT[(c + 1) * LDVT + r] = v.y;
                sVT[(c + 2) * LDVT + r] = v.z;
                sVT[(c + 3) * LDVT + r] = v.w;
            }
        }
        {   // k2 (masked): 8 threads per key row, 24 floats each
            int r = tid >> 3, seg = tid & 7;
            const float* p = sm + SK_OFF + (st & 1) * SK_SZ + r * LDK + seg * 24;
            float s = 0.f;
            #pragma unroll
            for (int i = 0; i < 6; i++) {
                float4 v = *(const float4*)(p + i * 4);
                float x0 = maskf(v.x), x1 = maskf(v.y), x2 = maskf(v.z), x3 = maskf(v.w);
                s += x0*x0 + x1*x1 + x2*x2 + x3*x3;
            }
            s += __shfl_xor_sync(0xffffffffu, s, 1);
            s += __shfl_xor_sync(0xffffffffu, s, 2);
            s += __shfl_xor_sync(0xffffffffu, s, 4);
            if (seg == 0) sK2[r] = s;
        }
        __syncthreads();                 // VT + k2 ready; rawV consumed

        if (st + 1 < NTILES) { prefetch_kv(smb, qkv, b, st + 1); CP_COMMIT(); }

        // ---- S = Q K^T (per warp: 16 rows x 32 keys) ----
        const uint32_t kb = kBase0 + (uint32_t)((st & 1) * SK_SZ) * 4;
        float sacc[4][4];
        #pragma unroll
        for (int n = 0; n < 4; n++) { sacc[n][0]=0.f; sacc[n][1]=0.f; sacc[n][2]=0.f; sacc[n][3]=0.f; }

        #pragma unroll
        for (int j = 0; j < 12; j++) {
            float4 alo = *(const float4*)(qlo + j * 4);
            float4 ahi = *(const float4*)(qhi + j * 4);
            #pragma unroll
            for (int h = 0; h < 2; h++) {
                uint32_t a0 = fu(h ? alo.z : alo.x);
                uint32_t a1 = fu(h ? ahi.z : ahi.x);
                uint32_t a2 = fu(h ? alo.w : alo.y);
                uint32_t a3 = fu(h ? ahi.w : ahi.y);
                const uint32_t coff = (uint32_t)(2 * j + h) * 32;
                #pragma unroll
                for (int p = 0; p < 2; p++) {
                    uint32_t b0, b1, b2, b3;
                    ldsm_x4(b0, b1, b2, b3, kb + (uint32_t)p * (16 * LDK * 4) + coff);
                    mma8(sacc[2*p],   a0, a1, a2, a3, b0, b1);
                    mma8(sacc[2*p+1], a0, a1, a2, a3, b2, b3);
                }
            }
        }

        // ---- softmax + PV per 8-key group ----
        #pragma unroll
        for (int n = 0; n < 4; n++) {
            float2 k2v = *(const float2*)(sK2 + n * 8 + 2 * t4);
            float d0 = fmaxf(fmaf(sacc[n][0], -2.f, q2a + k2v.x), 0.f);
            float d1 = fmaxf(fmaf(sacc[n][1], -2.f, q2a + k2v.y), 0.f);
            float d2 = fmaxf(fmaf(sacc[n][2], -2.f, q2b + k2v.x), 0.f);
            float d3 = fmaxf(fmaf(sacc[n][3], -2.f, q2b + k2v.y), 0.f);
            float p0 = maskf(ex2_approx(sqrt_approx(d0) * NEG_SCALE_LOG2E));
            float p1 = maskf(ex2_approx(sqrt_approx(d1) * NEG_SCALE_LOG2E));
            float p2 = maskf(ex2_approx(sqrt_approx(d2) * NEG_SCALE_LOG2E));
            float p3 = maskf(ex2_approx(sqrt_approx(d3) * NEG_SCALE_LOG2E));
            l0 += p0 + p1; l1 += p2 + p3;

            float v0 = __shfl_sync(0xffffffffu, p0, src_lo);
            float v1 = __shfl_sync(0xffffffffu, p1, src_lo);
            float w0 = __shfl_sync(0xffffffffu, p0, src_hi);
            float w1 = __shfl_sync(0xffffffffu, p1, src_hi);
            float x0 = __shfl_sync(0xffffffffu, p2, src_lo);
            float x1 = __shfl_sync(0xffffffffu, p3, src_lo);
            float y0 = __shfl_sync(0xffffffffu, p2, src_hi);
            float y1 = __shfl_sync(0xffffffffu, p3, src_hi);
            uint32_t pa0 = fu(oddc ? v1 : v0);
            uint32_t pa1 = fu(oddc ? x1 : x0);
            uint32_t pa2 = fu(oddc ? w1 : w0);
            uint32_t pa3 = fu(oddc ? y1 : y0);

            const uint32_t va = vtBase + (uint32_t)n * 32;
            #pragma unroll
            for (int q = 0; q < 12; q++) {
                uint32_t b0, b1, b2, b3;
                ldsm_x4(b0, b1, b2, b3, va + (uint32_t)q * (16 * LDVT * 4));
                mma8(o[2*q],   pa0, pa1, pa2, pa3, b0, b1);
                mma8(o[2*q+1], pa0, pa1, pa2, pa3, b2, b3);
            }
        }
    }

    // ---- epilogue ----
    l0 += __shfl_xor_sync(0xffffffffu, l0, 1);
    l0 += __shfl_xor_sync(0xffffffffu, l0, 2);
    l1 += __shfl_xor_sync(0xffffffffu, l1, 1);
    l1 += __shfl_xor_sync(0xffffffffu, l1, 2);
    float il0 = 1.f / l0, il1 = 1.f / l1;
    size_t orow0 = ((size_t)(b * NTOK + q0 + R + g)) * DIMC;
    size_t orow1 = orow0 + (size_t)8 * DIMC;
    #pragma unroll
    for (int nn = 0; nn < 24; nn++) {
        int col = nn * 8 + 2 * t4;
        *(float2*)(out + orow0 + col) = make_float2(o[nn][0] * il0, o[nn][1] * il0);
        *(float2*)(out + orow1 + col) = make_float2(o[nn][2] * il1, o[nn][3] * il1);
    }
}

extern "C" void kernel_launch(void* const* d_in, const int* in_sizes, int n_in,
                              void* d_out, int out_size) {
    const float* qkv = (const float*)d_in[0];
    float* out = (float*)d_out;
    cudaFuncSetAttribute(qkv_l2attn_kernel,
                         cudaFuncAttributeMaxDynamicSharedMemorySize, SMEM_BYTES);
    dim3 grid(NTOK / BR, NB);
    qkv_l2attn_kernel<<<grid, NTHREADS, SMEM_BYTES>>>(qkv, out);
}

// round 10
// speedup vs baseline: 1.2654x; 1.1658x over previous
#include <cuda_runtime.h>
#include <cstdint>
#include <cstddef>

#define DIMC 192
#define ROWSTRIDE 576
#define NB   8
#define NTOK 4096
#define BR   128
#define BC   32
#define NTILES (NTOK / BC)
#define NTHREADS 256
#define LDQ  208     /* permuted Q stride (floats) */
#define LDK  196     /* raw K stride               */
#define LDVR 204     /* raw V stride               */
#define LDVB 200     /* VB stride (uint32/f16x2): 200%32==8 -> banks 8*t4+g */
#define NEG_SCALE_LOG2E (-0.104117549f)   /* -(192^-0.5)*log2(e) */

// ---- smem layout (float units) ----
#define SQ_OFF   0
#define SQ_SZ    (BR * LDQ)              /* 26624 */
#define SK_OFF   (SQ_OFF + SQ_SZ)
#define SK_SZ    (BC * LDK)              /* 6272 x2 */
#define SVR_OFF  (SK_OFF + 2 * SK_SZ)
#define SVR_SZ   (BC * LDVR)             /* 6528 */
#define SVB_OFF  (SVR_OFF + SVR_SZ)
#define SVB_SZ   (16 * LDVB)             /* 3200 uint32 */
#define SK2_OFF  (SVB_OFF + SVB_SZ)      /* 32  */
#define SQ2_OFF  (SK2_OFF + 32)          /* 128 */
#define SMEM_FLOATS (SQ2_OFF + 128)
#define SMEM_BYTES  (SMEM_FLOATS * 4)    /* 196,224 B */

__device__ __forceinline__ uint32_t fu(float f) { return __float_as_uint(f); }
__device__ __forceinline__ float maskf(float x) {
    return __uint_as_float(__float_as_uint(x) & 0xFFFFE000u);   /* tf32 trunc */
}
__device__ __forceinline__ float sqrt_approx(float x) {
    float r; asm("sqrt.approx.f32 %0, %1;" : "=f"(r) : "f"(x)); return r;
}
__device__ __forceinline__ float ex2_approx(float x) {
    float r; asm("ex2.approx.f32 %0, %1;" : "=f"(r) : "f"(x)); return r;
}
__device__ __forceinline__ uint32_t pack_f16(float lo, float hi) {
    uint32_t d;
    asm("cvt.rn.f16x2.f32 %0, %1, %2;" : "=r"(d) : "f"(hi), "f"(lo));
    return d;
}
__device__ __forceinline__ uint32_t smem_u32(const void* p) {
    uint32_t a;
    asm("{ .reg .u64 t; cvta.to.shared.u64 t, %1; cvt.u32.u64 %0, t; }" : "=r"(a) : "l"(p));
    return a;
}

#define CP_ASYNC16(dst, src) \
    asm volatile("cp.async.cg.shared.global [%0], [%1], 16;" :: "r"(dst), "l"(src) : "memory")
#define CP_COMMIT() asm volatile("cp.async.commit_group;" ::: "memory")
#define CP_WAIT0()  asm volatile("cp.async.wait_group 0;" ::: "memory")

__device__ __forceinline__ void mma8_tf32(float* c,
        uint32_t a0, uint32_t a1, uint32_t a2, uint32_t a3,
        uint32_t b0, uint32_t b1) {
    asm volatile("mma.sync.aligned.m16n8k8.row.col.f32.tf32.tf32.f32 "
        "{%0,%1,%2,%3}, {%4,%5,%6,%7}, {%8,%9}, {%0,%1,%2,%3};"
        : "+f"(c[0]), "+f"(c[1]), "+f"(c[2]), "+f"(c[3])
        : "r"(a0), "r"(a1), "r"(a2), "r"(a3), "r"(b0), "r"(b1));
}

__device__ __forceinline__ void mma16_f16(float* c,
        uint32_t a0, uint32_t a1, uint32_t a2, uint32_t a3,
        uint32_t b0, uint32_t b1) {
    asm volatile("mma.sync.aligned.m16n8k16.row.col.f32.f16.f16.f32 "
        "{%0,%1,%2,%3}, {%4,%5,%6,%7}, {%8,%9}, {%0,%1,%2,%3};"
        : "+f"(c[0]), "+f"(c[1]), "+f"(c[2]), "+f"(c[3])
        : "r"(a0), "r"(a1), "r"(a2), "r"(a3), "r"(b0), "r"(b1));
}

// prefetch raw K (double-buffered) + raw V (single buffer) for tile st
__device__ __forceinline__ void prefetch_kv(uint32_t smb, const float* __restrict__ qkv,
                                            int b, int st) {
    const int tid = threadIdx.x;
    const float* base = qkv + ((size_t)(b * NTOK + st * BC)) * ROWSTRIDE + DIMC;
    const uint32_t kd = smb + (SK_OFF + (st & 1) * SK_SZ) * 4;
    const uint32_t vd = smb + SVR_OFF * 4;
    #pragma unroll
    for (int i = 0; i < 6; i++) {
        int idx = tid + i * NTHREADS;      // 1536 = 32 rows x 48 float4
        int r = idx / 48, c = (idx - r * 48) * 4;
        CP_ASYNC16(kd + (uint32_t)(r * LDK + c) * 4, base + (size_t)r * ROWSTRIDE + c);
    }
    #pragma unroll
    for (int i = 0; i < 6; i++) {
        int idx = tid + i * NTHREADS;
        int r = idx / 48, c = (idx - r * 48) * 4;
        CP_ASYNC16(vd + (uint32_t)(r * LDVR + c) * 4, base + (size_t)r * ROWSTRIDE + DIMC + c);
    }
}

__global__ void __launch_bounds__(NTHREADS, 1)
qkv_l2attn_kernel(const float* __restrict__ qkv, float* __restrict__ out)
{
    extern __shared__ float sm[];
    float*    sQ  = sm + SQ_OFF;
    float*    sVR = sm + SVR_OFF;
    uint32_t* sVB = (uint32_t*)(sm + SVB_OFF);
    float*    sK2 = sm + SK2_OFF;
    float*    sQ2 = sm + SQ2_OFF;
    const uint32_t smb = smem_u32(sm);

    const int tid  = threadIdx.x;
    const int warp = tid >> 5;
    const int lane = tid & 31;
    const int g    = lane >> 2;
    const int t4   = lane & 3;
    const int R    = warp * 16;

    const int b  = blockIdx.y;
    const int q0 = blockIdx.x * BR;

    // ---- prologue ----
    prefetch_kv(smb, qkv, b, 0);
    CP_COMMIT();

    // Q -> permuted smem (raw fp32): col c -> block (c&3)*52, pos (c>>3)*2 + ((c>>2)&1)
    const float* qptr = qkv + ((size_t)(b * NTOK + q0)) * ROWSTRIDE;
    #pragma unroll
    for (int it = 0; it < 24; it++) {
        int idx = tid * 4 + it * (NTHREADS * 4);
        int r = idx / DIMC, c = idx - r * DIMC;
        float4 v = *(const float4*)(qptr + (size_t)r * ROWSTRIDE + c);
        int base = (c >> 3) * 2 + ((c >> 2) & 1);
        float* row = sQ + r * LDQ + base;
        row[0]   = v.x;
        row[52]  = v.y;
        row[104] = v.z;
        row[156] = v.w;
    }
    __syncthreads();
    {   // q2 (tf32-masked): 2 threads per row
        int r = tid >> 1, hb = tid & 1;
        float s = 0.f;
        #pragma unroll
        for (int bb = 0; bb < 2; bb++) {
            const float* p = sQ + r * LDQ + (hb * 2 + bb) * 52;
            #pragma unroll
            for (int i = 0; i < 12; i++) {
                float4 v = *(const float4*)(p + i * 4);
                float x0 = maskf(v.x), x1 = maskf(v.y), x2 = maskf(v.z), x3 = maskf(v.w);
                s += x0*x0 + x1*x1 + x2*x2 + x3*x3;
            }
        }
        s += __shfl_xor_sync(0xffffffffu, s, 1);
        if (hb == 0) sQ2[r] = s;
    }
    __syncthreads();

    const float q2a = sQ2[R + g];
    const float q2b = sQ2[R + 8 + g];

    float l0 = 0.f, l1 = 0.f;
    float o[24][4];
    #pragma unroll
    for (int n = 0; n < 24; n++) { o[n][0]=0.f; o[n][1]=0.f; o[n][2]=0.f; o[n][3]=0.f; }

    const float* qlo = sQ + (R + g) * LDQ + t4 * 52;
    const float* qhi = qlo + 8 * LDQ;

    for (int st = 0; st < NTILES; ++st) {
        const float* sK = sm + SK_OFF + (st & 1) * SK_SZ;

        CP_WAIT0();
        __syncthreads();                 // K(st) + rawV(st) visible; PV(st-1) readers done

        {   // repack rawV (f32) -> sVB (f16x2 pairs along key): 16 thr per key-pair
            int j = tid >> 4, cb = tid & 15;
            #pragma unroll
            for (int i = 0; i < 3; i++) {
                int c = cb * 4 + i * 64;
                float4 ve = *(const float4*)(sVR + (2 * j)     * LDVR + c);
                float4 vo = *(const float4*)(sVR + (2 * j + 1) * LDVR + c);
                uint32_t* dst = sVB + j * LDVB + c;
                dst[0] = pack_f16(ve.x, vo.x);
                dst[1] = pack_f16(ve.y, vo.y);
                dst[2] = pack_f16(ve.z, vo.z);
                dst[3] = pack_f16(ve.w, vo.w);
            }
        }
        {   // k2 (tf32-masked): 8 threads per key row
            int r = tid >> 3, seg = tid & 7;
            const float* p = sK + r * LDK + seg * 24;
            float s = 0.f;
            #pragma unroll
            for (int i = 0; i < 6; i++) {
                float4 v = *(const float4*)(p + i * 4);
                float x0 = maskf(v.x), x1 = maskf(v.y), x2 = maskf(v.z), x3 = maskf(v.w);
                s += x0*x0 + x1*x1 + x2*x2 + x3*x3;
            }
            s += __shfl_xor_sync(0xffffffffu, s, 1);
            s += __shfl_xor_sync(0xffffffffu, s, 2);
            s += __shfl_xor_sync(0xffffffffu, s, 4);
            if (seg == 0) sK2[r] = s;
        }
        __syncthreads();                 // VB + k2 ready; rawV free

        if (st + 1 < NTILES) { prefetch_kv(smb, qkv, b, st + 1); CP_COMMIT(); }

        // ---- S = Q K^T (per warp: 16 rows x 32 keys), tf32 ----
        float sacc[4][4];
        #pragma unroll
        for (int n = 0; n < 4; n++) { sacc[n][0]=0.f; sacc[n][1]=0.f; sacc[n][2]=0.f; sacc[n][3]=0.f; }

        #pragma unroll
        for (int j = 0; j < 12; j++) {
            float4 alo = *(const float4*)(qlo + j * 4);
            float4 ahi = *(const float4*)(qhi + j * 4);
            #pragma unroll
            for (int h = 0; h < 2; h++) {
                uint32_t a0 = fu(h ? alo.z : alo.x);
                uint32_t a1 = fu(h ? ahi.z : ahi.x);
                uint32_t a2 = fu(h ? alo.w : alo.y);
                uint32_t a3 = fu(h ? ahi.w : ahi.y);
                const int kk = (2 * j + h) * 8;
                #pragma unroll
                for (int n = 0; n < 4; n++) {
                    uint32_t b0 = fu(sK[(n * 8 + g) * LDK + kk + t4]);
                    uint32_t b1 = fu(sK[(n * 8 + g) * LDK + kk + 4 + t4]);
                    mma8_tf32(sacc[n], a0, a1, a2, a3, b0, b1);
                }
            }
        }

        // ---- softmax + fp16 PV per 16-key half ----
        #pragma unroll
        for (int t = 0; t < 2; t++) {
            float pr[2][4];
            #pragma unroll
            for (int u = 0; u < 2; u++) {
                const int n = 2 * t + u;
                float2 k2v = *(const float2*)(sK2 + n * 8 + 2 * t4);
                float d0 = fmaxf(fmaf(sacc[n][0], -2.f, q2a + k2v.x), 0.f);
                float d1 = fmaxf(fmaf(sacc[n][1], -2.f, q2a + k2v.y), 0.f);
                float d2 = fmaxf(fmaf(sacc[n][2], -2.f, q2b + k2v.x), 0.f);
                float d3 = fmaxf(fmaf(sacc[n][3], -2.f, q2b + k2v.y), 0.f);
                pr[u][0] = ex2_approx(sqrt_approx(d0) * NEG_SCALE_LOG2E);
                pr[u][1] = ex2_approx(sqrt_approx(d1) * NEG_SCALE_LOG2E);
                pr[u][2] = ex2_approx(sqrt_approx(d2) * NEG_SCALE_LOG2E);
                pr[u][3] = ex2_approx(sqrt_approx(d3) * NEG_SCALE_LOG2E);
                l0 += pr[u][0] + pr[u][1];
                l1 += pr[u][2] + pr[u][3];
            }
            // C-layout == f16 A-layout: zero-shuffle re-fragmentation
            uint32_t pa0 = pack_f16(pr[0][0], pr[0][1]);   // (g,   keys 16t+2t4..+1)
            uint32_t pa1 = pack_f16(pr[0][2], pr[0][3]);   // (g+8, same)
            uint32_t pa2 = pack_f16(pr[1][0], pr[1][1]);   // (g,   keys 16t+8+2t4..+1)
            uint32_t pa3 = pack_f16(pr[1][2], pr[1][3]);   // (g+8, same)

            const uint32_t* vb0 = sVB + (8 * t + t4)     * LDVB + g;
            const uint32_t* vb1 = sVB + (8 * t + 4 + t4) * LDVB + g;
            #pragma unroll
            for (int nn = 0; nn < 24; nn++) {
                uint32_t b0 = vb0[nn * 8];
                uint32_t b1 = vb1[nn * 8];
                mma16_f16(o[nn], pa0, pa1, pa2, pa3, b0, b1);
            }
        }
    }

    // ---- epilogue ----
    l0 += __shfl_xor_sync(0xffffffffu, l0, 1);
    l0 += __shfl_xor_sync(0xffffffffu, l0, 2);
    l1 += __shfl_xor_sync(0xffffffffu, l1, 1);
    l1 += __shfl_xor_sync(0xffffffffu, l1, 2);
    float il0 = 1.f / l0, il1 = 1.f / l1;
    size_t orow0 = ((size_t)(b * NTOK + q0 + R + g)) * DIMC;
    size_t orow1 = orow0 + (size_t)8 * DIMC;
    #pragma unroll
    for (int nn = 0; nn < 24; nn++) {
        int col = nn * 8 + 2 * t4;
        *(float2*)(out + orow0 + col) = make_float2(o[nn][0] * il0, o[nn][1] * il0);
        *(float2*)(out + orow1 + col) = make_float2(o[nn][2] * il1, o[nn][3] * il1);
    }
}

extern "C" void kernel_launch(void* const* d_in, const int* in_sizes, int n_in,
                              void* d_out, int out_size) {
    const float* qkv = (const float*)d_in[0];
    float* out = (float*)d_out;
    cudaFuncSetAttribute(qkv_l2attn_kernel,
                         cudaFuncAttributeMaxDynamicSharedMemorySize, SMEM_BYTES);
    dim3 grid(NTOK / BR, NB);
    qkv_l2attn_kernel<<<grid, NTHREADS, SMEM_BYTES>>>(qkv, out);
}

// round 11
// speedup vs baseline: 1.5468x; 1.2224x over previous
#include <cuda_runtime.h>
#include <cuda_fp16.h>
#include <cstdint>
#include <cstddef>

#define DIMC 192
#define ROWSTRIDE 576
#define NB   8
#define NTOK 4096
#define BR   128
#define BC   64
#define NTILES (NTOK / BC)
#define NTHREADS 256
#define NEG_SCALE_LOG2E (-0.104117549f)   /* -(192^-0.5)*log2(e) */

// pair-permuted f16x2 layout: pair p -> (p&3)*28 + ((p>>3)<<1) + ((p>>2)&1); row stride 112
#define LDH   112
#define LDKR  196    /* raw K stride (f32) */
#define LDVR  204    /* raw V stride (f32) */
#define LDVB  200    /* VB stride (u32)    */

// ---- smem layout (uint32 units) ----
#define QH_OFF   0                        /* 128*112 = 14336 */
#define KH_OFF   14336                    /* 64*112  = 7168  */
#define RK_OFF   21504                    /* 64*196  = 12544 */
#define RV_OFF   34048                    /* 64*204  = 13056 */
#define VB_OFF   47104                    /* 32*200  = 6400  */
#define K2_OFF   53504                    /* 64  */
#define Q2_OFF   53568                    /* 128 */
#define SMEM_U32 53696
#define SMEM_BYTES (SMEM_U32 * 4)         /* 214,784 B */

__device__ __forceinline__ float sqrt_approx(float x) {
    float r; asm("sqrt.approx.f32 %0, %1;" : "=f"(r) : "f"(x)); return r;
}
__device__ __forceinline__ float ex2_approx(float x) {
    float r; asm("ex2.approx.f32 %0, %1;" : "=f"(r) : "f"(x)); return r;
}
__device__ __forceinline__ uint32_t pack_f16(float lo, float hi) {
    uint32_t d;
    asm("cvt.rn.f16x2.f32 %0, %1, %2;" : "=r"(d) : "f"(hi), "f"(lo));
    return d;
}
// pack and accumulate sum of squares of the ROUNDED values
__device__ __forceinline__ uint32_t pack2q(float lo, float hi, float& sq) {
    uint32_t u = pack_f16(lo, hi);
    __half2 h = *reinterpret_cast<__half2*>(&u);
    float2 f = __half22float2(h);
    sq += f.x * f.x + f.y * f.y;
    return u;
}
__device__ __forceinline__ uint32_t smem_u32p(const void* p) {
    uint32_t a;
    asm("{ .reg .u64 t; cvta.to.shared.u64 t, %1; cvt.u32.u64 %0, t; }" : "=r"(a) : "l"(p));
    return a;
}
__device__ __forceinline__ int offp(int p) {
    return (p & 3) * 28 + ((p >> 3) << 1) + ((p >> 2) & 1);
}

#define CP_ASYNC16(dst, src) \
    asm volatile("cp.async.cg.shared.global [%0], [%1], 16;" :: "r"(dst), "l"(src) : "memory")
#define CP_COMMIT() asm volatile("cp.async.commit_group;" ::: "memory")
#define CP_WAIT0()  asm volatile("cp.async.wait_group 0;" ::: "memory")

__device__ __forceinline__ void mma16_f16(float* c,
        uint32_t a0, uint32_t a1, uint32_t a2, uint32_t a3,
        uint32_t b0, uint32_t b1) {
    asm volatile("mma.sync.aligned.m16n8k16.row.col.f32.f16.f16.f32 "
        "{%0,%1,%2,%3}, {%4,%5,%6,%7}, {%8,%9}, {%0,%1,%2,%3};"
        : "+f"(c[0]), "+f"(c[1]), "+f"(c[2]), "+f"(c[3])
        : "r"(a0), "r"(a1), "r"(a2), "r"(a3), "r"(b0), "r"(b1));
}

// prefetch raw K + raw V (f32) for tile st into the single raw buffers
__device__ __forceinline__ void prefetch_kv(uint32_t smb, const float* __restrict__ qkv,
                                            int b, int st) {
    const int tid = threadIdx.x;
    const float* base = qkv + ((size_t)(b * NTOK + st * BC)) * ROWSTRIDE + DIMC;
    const uint32_t kd = smb + RK_OFF * 4;
    const uint32_t vd = smb + RV_OFF * 4;
    #pragma unroll
    for (int i = 0; i < 12; i++) {
        int idx = tid + i * NTHREADS;          // 3072 = 64 rows x 48 float4
        int r = idx / 48, c = (idx - r * 48) * 4;
        CP_ASYNC16(kd + (uint32_t)(r * LDKR + c) * 4, base + (size_t)r * ROWSTRIDE + c);
    }
    #pragma unroll
    for (int i = 0; i < 12; i++) {
        int idx = tid + i * NTHREADS;
        int r = idx / 48, c = (idx - r * 48) * 4;
        CP_ASYNC16(vd + (uint32_t)(r * LDVR + c) * 4, base + (size_t)r * ROWSTRIDE + DIMC + c);
    }
}

__global__ void __launch_bounds__(NTHREADS, 1)
qkv_l2attn_kernel(const float* __restrict__ qkv, float* __restrict__ out)
{
    extern __shared__ uint32_t smu[];
    uint32_t* sQH = smu + QH_OFF;
    uint32_t* sKH = smu + KH_OFF;
    float*    sRK = (float*)(smu + RK_OFF);
    float*    sRV = (float*)(smu + RV_OFF);
    uint32_t* sVB = smu + VB_OFF;
    float*    sK2 = (float*)(smu + K2_OFF);
    float*    sQ2 = (float*)(smu + Q2_OFF);
    const uint32_t smb = smem_u32p(smu);

    const int tid  = threadIdx.x;
    const int warp = tid >> 5;
    const int lane = tid & 31;
    const int g    = lane >> 2;
    const int t4   = lane & 3;
    const int R    = warp * 16;

    const int b  = blockIdx.y;
    const int q0 = blockIdx.x * BR;

    // ---- prologue: prefetch tile 0, pack Q -> f16x2 permuted, q2 from rounded vals ----
    prefetch_kv(smb, qkv, b, 0);
    CP_COMMIT();
    {
        int r = tid >> 1, hf = tid & 1;
        const float* qrow = qkv + ((size_t)(b * NTOK + q0 + r)) * ROWSTRIDE + hf * 96;
        uint32_t* qdst = sQH + r * LDH;
        float s = 0.f;
        #pragma unroll
        for (int i = 0; i < 24; i++) {
            float4 v = *(const float4*)(qrow + i * 4);
            int p = hf * 48 + i * 2;
            qdst[offp(p)]     = pack2q(v.x, v.y, s);
            qdst[offp(p + 1)] = pack2q(v.z, v.w, s);
        }
        s += __shfl_xor_sync(0xffffffffu, s, 1);
        if (hf == 0) sQ2[r] = s;
    }
    __syncthreads();

    const float q2a = sQ2[R + g];
    const float q2b = sQ2[R + 8 + g];

    float l0 = 0.f, l1 = 0.f;
    float o[24][4];
    #pragma unroll
    for (int n = 0; n < 24; n++) { o[n][0]=0.f; o[n][1]=0.f; o[n][2]=0.f; o[n][3]=0.f; }

    const uint32_t* qloPtr = sQH + (R + g) * LDH + t4 * 28;
    const uint32_t* qhiPtr = qloPtr + 8 * LDH;
    const uint32_t* kPtr   = sKH + g * LDH + t4 * 28;

    for (int st = 0; st < NTILES; ++st) {
        CP_WAIT0();
        __syncthreads();               // raw K/V(st) ready; compute(st-1) done

        {   // repack K: raw f32 -> f16x2 permuted + k2 (rounded)
            int r = tid >> 2, q4 = tid & 3;
            const float* krow = sRK + r * LDKR + q4 * 48;
            uint32_t* kdst = sKH + r * LDH;
            float s = 0.f;
            #pragma unroll
            for (int i = 0; i < 12; i++) {
                float4 v = *(const float4*)(krow + i * 4);
                int p = q4 * 24 + i * 2;
                kdst[offp(p)]     = pack2q(v.x, v.y, s);
                kdst[offp(p + 1)] = pack2q(v.z, v.w, s);
            }
            s += __shfl_xor_sync(0xffffffffu, s, 1);
            s += __shfl_xor_sync(0xffffffffu, s, 2);
            if (q4 == 0) sK2[r] = s;
        }
        {   // repack V: raw f32 -> f16x2 (key pairs along low bits)
            int kp = tid >> 3, u8 = tid & 7;
            const float* ve = sRV + (2 * kp) * LDVR + u8 * 24;
            const float* vo = ve + LDVR;
            uint32_t* vdst = sVB + kp * LDVB + u8 * 24;
            #pragma unroll
            for (int i = 0; i < 6; i++) {
                float4 a = *(const float4*)(ve + i * 4);
                float4 c = *(const float4*)(vo + i * 4);
                uint4 w;
                w.x = pack_f16(a.x, c.x);
                w.y = pack_f16(a.y, c.y);
                w.z = pack_f16(a.z, c.z);
                w.w = pack_f16(a.w, c.w);
                *(uint4*)(vdst + i * 4) = w;
            }
        }
        __syncthreads();               // KH/VB/k2 visible; raw buffers consumed

        if (st + 1 < NTILES) { prefetch_kv(smb, qkv, b, st + 1); CP_COMMIT(); }

        // ---- S = Q K^T (per warp: 16 rows x 64 keys), fp16 MMA ----
        float sacc[8][4];
        #pragma unroll
        for (int n = 0; n < 8; n++) { sacc[n][0]=0.f; sacc[n][1]=0.f; sacc[n][2]=0.f; sacc[n][3]=0.f; }

        #pragma unroll
        for (int i = 0; i < 6; i++) {
            uint4 ql = *(const uint4*)(qloPtr + 4 * i);
            uint4 qh = *(const uint4*)(qhiPtr + 4 * i);
            #pragma unroll
            for (int n = 0; n < 8; n++) {
                uint4 kb = *(const uint4*)(kPtr + n * (8 * LDH) + 4 * i);
                mma16_f16(sacc[n], ql.x, qh.x, ql.y, qh.y, kb.x, kb.y);   // k chunk 2i
                mma16_f16(sacc[n], ql.z, qh.z, ql.w, qh.w, kb.z, kb.w);   // k chunk 2i+1
            }
        }

        // ---- softmax + fp16 PV per 16-key group ----
        #pragma unroll
        for (int t = 0; t < 4; t++) {
            float pr[2][4];
            #pragma unroll
            for (int u = 0; u < 2; u++) {
                const int n = 2 * t + u;
                float2 k2v = *(const float2*)(sK2 + n * 8 + 2 * t4);
                float d0 = fmaxf(fmaf(sacc[n][0], -2.f, q2a + k2v.x), 0.f);
                float d1 = fmaxf(fmaf(sacc[n][1], -2.f, q2a + k2v.y), 0.f);
                float d2 = fmaxf(fmaf(sacc[n][2], -2.f, q2b + k2v.x), 0.f);
                float d3 = fmaxf(fmaf(sacc[n][3], -2.f, q2b + k2v.y), 0.f);
                pr[u][0] = ex2_approx(sqrt_approx(d0) * NEG_SCALE_LOG2E);
                pr[u][1] = ex2_approx(sqrt_approx(d1) * NEG_SCALE_LOG2E);
                pr[u][2] = ex2_approx(sqrt_approx(d2) * NEG_SCALE_LOG2E);
                pr[u][3] = ex2_approx(sqrt_approx(d3) * NEG_SCALE_LOG2E);
                l0 += pr[u][0] + pr[u][1];
                l1 += pr[u][2] + pr[u][3];
            }
            uint32_t pa0 = pack_f16(pr[0][0], pr[0][1]);
            uint32_t pa1 = pack_f16(pr[0][2], pr[0][3]);
            uint32_t pa2 = pack_f16(pr[1][0], pr[1][1]);
            uint32_t pa3 = pack_f16(pr[1][2], pr[1][3]);

            const uint32_t* vb0 = sVB + (8 * t + t4)     * LDVB + g;
            const uint32_t* vb1 = sVB + (8 * t + 4 + t4) * LDVB + g;
            #pragma unroll
            for (int nn = 0; nn < 24; nn++) {
                uint32_t b0 = vb0[nn * 8];
                uint32_t b1 = vb1[nn * 8];
                mma16_f16(o[nn], pa0, pa1, pa2, pa3, b0, b1);
            }
        }
    }

    // ---- epilogue ----
    l0 += __shfl_xor_sync(0xffffffffu, l0, 1);
    l0 += __shfl_xor_sync(0xffffffffu, l0, 2);
    l1 += __shfl_xor_sync(0xffffffffu, l1, 1);
    l1 += __shfl_xor_sync(0xffffffffu, l1, 2);
    float il0 = 1.f / l0, il1 = 1.f / l1;
    size_t orow0 = ((size_t)(b * NTOK + q0 + R + g)) * DIMC;
    size_t orow1 = orow0 + (size_t)8 * DIMC;
    #pragma unroll
    for (int nn = 0; nn < 24; nn++) {
        int col = nn * 8 + 2 * t4;
        *(float2*)(out + orow0 + col) = make_float2(o[nn][0] * il0, o[nn][1] * il0);
        *(float2*)(out + orow1 + col) = make_float2(o[nn][2] * il1, o[nn][3] * il1);
    }
}

extern "C" void kernel_launch(void* const* d_in, const int* in_sizes, int n_in,
                              void* d_out, int out_size) {
    const float* qkv = (const float*)d_in[0];
    float* out = (float*)d_out;
    cudaFuncSetAttribute(qkv_l2attn_kernel,
                         cudaFuncAttributeMaxDynamicSharedMemorySize, SMEM_BYTES);
    dim3 grid(NTOK / BR, NB);
    qkv_l2attn_kernel<<<grid, NTHREADS, SMEM_BYTES>>>(qkv, out);
}

// round 12
// speedup vs baseline: 2.3637x; 1.5281x over previous
#include <cuda_runtime.h>
#include <cuda_fp16.h>
#include <cstdint>
#include <cstddef>

#define DIMC 192
#define ROWSTRIDE 576
#define NB   8
#define NTOK 4096
#define BR   128
#define BC   64
#define NTILES (NTOK / BC)
#define NTHREADS 256
#define NEG_SCALE_LOG2E (-0.104117549f)   /* -(192^-0.5)*log2(e) */

#define LDH   112      /* K/Q fp16x2 row stride (u32); slot(p) = (p&3)*28 + (p>>2) */
#define LDV2  388      /* smem V row stride (u32); 388 % 32 == 4 -> conflict-free PV LDS.128 */
#define VROW  192      /* gmem vhalf compact row (u32); slot24(c) = (c&7)*24 + (c>>3) */

// ---- smem layout (u32 units) ----
#define QH_OFF  0
#define QH_SZ   (BR * LDH)          /* 14336 */
#define KH_OFF  (QH_OFF + QH_SZ)
#define KH_SZ   (BC * LDH)          /* 7168 x2 */
#define VB_OFF  (KH_OFF + 2 * KH_SZ)
#define VB_SZ   (32 * LDV2)         /* 12416 x2 */
#define K2_OFF  (VB_OFF + 2 * VB_SZ)   /* 2 x 64 */
#define Q2_OFF  (K2_OFF + 128)         /* 128 */
#define SMEM_U32 (Q2_OFF + 128)
#define SMEM_BYTES (SMEM_U32 * 4)      /* 215,040 B */

// ---- device scratch (converted operands; written by prepass) ----
__device__ uint32_t g_khalf[(size_t)NB * NTOK * LDH];
__device__ uint32_t g_vhalf[(size_t)NB * (NTOK / 2) * VROW];
__device__ float    g_k2[NB * NTOK];

__device__ __forceinline__ float sqrt_approx(float x) {
    float r; asm("sqrt.approx.f32 %0, %1;" : "=f"(r) : "f"(x)); return r;
}
__device__ __forceinline__ float ex2_approx(float x) {
    float r; asm("ex2.approx.f32 %0, %1;" : "=f"(r) : "f"(x)); return r;
}
__device__ __forceinline__ uint32_t pack_f16(float lo, float hi) {
    uint32_t d;
    asm("cvt.rn.f16x2.f32 %0, %1, %2;" : "=r"(d) : "f"(hi), "f"(lo));
    return d;
}
// pack and accumulate sum of squares of the ROUNDED values
__device__ __forceinline__ uint32_t pack2q(float lo, float hi, float& sq) {
    uint32_t u = pack_f16(lo, hi);
    __half2 h = *reinterpret_cast<__half2*>(&u);
    float2 f = __half22float2(h);
    sq += f.x * f.x + f.y * f.y;
    return u;
}
__device__ __forceinline__ uint32_t smem_u32p(const void* p) {
    uint32_t a;
    asm("{ .reg .u64 t; cvta.to.shared.u64 t, %1; cvt.u32.u64 %0, t; }" : "=r"(a) : "l"(p));
    return a;
}

#define CP_ASYNC16(dst, src) \
    asm volatile("cp.async.cg.shared.global [%0], [%1], 16;" :: "r"(dst), "l"(src) : "memory")
#define CP_COMMIT() asm volatile("cp.async.commit_group;" ::: "memory")
#define CP_WAIT0()  asm volatile("cp.async.wait_group 0;" ::: "memory")

__device__ __forceinline__ void mma16_f16(float* c,
        uint32_t a0, uint32_t a1, uint32_t a2, uint32_t a3,
        uint32_t b0, uint32_t b1) {
    asm volatile("mma.sync.aligned.m16n8k16.row.col.f32.f16.f16.f32 "
        "{%0,%1,%2,%3}, {%4,%5,%6,%7}, {%8,%9}, {%0,%1,%2,%3};"
        : "+f"(c[0]), "+f"(c[1]), "+f"(c[2]), "+f"(c[3])
        : "r"(a0), "r"(a1), "r"(a2), "r"(a3), "r"(b0), "r"(b1));
}

// ============ prepass: convert K/V to fp16 pair layouts + k2 ============
__global__ void __launch_bounds__(256)
prepass_kernel(const float* __restrict__ qkv)
{
    const int b   = blockIdx.y;
    const int t0  = blockIdx.x * 64;
    const int tid = threadIdx.x;

    // --- K: 4 threads per row; write pre-permuted fp16x2 + k2 (rounded) ---
    {
        int r = tid >> 2, q4 = tid & 3;
        int t = t0 + r;
        const float* krow = qkv + ((size_t)(b * NTOK + t)) * ROWSTRIDE + DIMC + q4 * 48;
        uint32_t* kdst = g_khalf + ((size_t)(b * NTOK + t)) * LDH;
        float s = 0.f;
        #pragma unroll
        for (int i = 0; i < 12; i++) {
            float4 v = *(const float4*)(krow + i * 4);
            int p0 = q4 * 24 + 2 * i, p1 = p0 + 1;
            kdst[(p0 & 3) * 28 + (p0 >> 2)] = pack2q(v.x, v.y, s);
            kdst[(p1 & 3) * 28 + (p1 >> 2)] = pack2q(v.z, v.w, s);
        }
        s += __shfl_xor_sync(0xffffffffu, s, 1);
        s += __shfl_xor_sync(0xffffffffu, s, 2);
        if (q4 == 0) g_k2[b * NTOK + t] = s;
    }
    // --- V: 8 threads per key pair; write key-pair fp16x2 in slot24 layout ---
    {
        int kp = tid >> 3, u8 = tid & 7;
        int tkey = t0 + 2 * kp;
        const float* ve = qkv + ((size_t)(b * NTOK + tkey)) * ROWSTRIDE + 2 * DIMC + u8 * 24;
        const float* vo = ve + ROWSTRIDE;
        uint32_t* vdst = g_vhalf + ((size_t)(b * (NTOK / 2) + (t0 >> 1) + kp)) * VROW;
        #pragma unroll
        for (int i = 0; i < 6; i++) {
            float4 a = *(const float4*)(ve + i * 4);
            float4 c4 = *(const float4*)(vo + i * 4);
            int c = u8 * 24 + i * 4;
            int blk = c & 7, rr = c >> 3;       // c%8 in {0,4}; no 8-boundary crossing
            vdst[(blk + 0) * 24 + rr] = pack_f16(a.x, c4.x);
            vdst[(blk + 1) * 24 + rr] = pack_f16(a.y, c4.y);
            vdst[(blk + 2) * 24 + rr] = pack_f16(a.z, c4.z);
            vdst[(blk + 3) * 24 + rr] = pack_f16(a.w, c4.w);
        }
    }
}

// prefetch converted K/V/k2 for tile st into buffer (st & 1)
__device__ __forceinline__ void prefetch_tile(uint32_t smb, int b, int st) {
    const int tid = threadIdx.x;
    const int buf = st & 1;
    const uint32_t* ksrc = g_khalf + ((size_t)(b * NTOK + st * BC)) * LDH;
    const uint32_t  kdst = smb + (KH_OFF + buf * KH_SZ) * 4;
    #pragma unroll
    for (int i = 0; i < 7; i++) {        // 64 rows x 28 chunks = 1792
        int cid = tid + i * NTHREADS;
        int r = cid / 28, off = (cid - r * 28) * 4;
        CP_ASYNC16(kdst + (uint32_t)(r * LDH + off) * 4, ksrc + (size_t)r * LDH + off);
    }
    const uint32_t* vsrc = g_vhalf + ((size_t)(b * (NTOK / 2) + st * 32)) * VROW;
    const uint32_t  vdst = smb + (VB_OFF + buf * VB_SZ) * 4;
    #pragma unroll
    for (int i = 0; i < 6; i++) {        // 32 kp x 48 chunks = 1536
        int cid = tid + i * NTHREADS;
        int kp = cid / 48, j = cid - kp * 48;
        int jq = j / 6, jr = j - jq * 6;     // compact slot24 -> padded slot48 remap
        CP_ASYNC16(vdst + (uint32_t)(kp * LDV2 + jq * 48 + jr * 4) * 4,
                   vsrc + (size_t)kp * VROW + j * 4);
    }
    if (tid < 16) {
        CP_ASYNC16(smb + (K2_OFF + buf * 64 + tid * 4) * 4,
                   g_k2 + b * NTOK + st * BC + tid * 4);
    }
}

__global__ void __launch_bounds__(NTHREADS, 1)
qkv_l2attn_kernel(const float* __restrict__ qkv, float* __restrict__ out)
{
    extern __shared__ uint32_t smu[];
    uint32_t* sQH = smu + QH_OFF;
    uint32_t* sKH = smu + KH_OFF;
    uint32_t* sVB = smu + VB_OFF;
    float*    sK2 = (float*)(smu + K2_OFF);
    float*    sQ2 = (float*)(smu + Q2_OFF);
    const uint32_t smb = smem_u32p(smu);

    const int tid  = threadIdx.x;
    const int warp = tid >> 5;
    const int lane = tid & 31;
    const int g    = lane >> 2;
    const int t4   = lane & 3;
    const int R    = warp * 16;

    const int b  = blockIdx.y;
    const int q0 = blockIdx.x * BR;

    // ---- prologue: prefetch tile 0 + pack Q (fp16 permuted) + q2 (rounded) ----
    prefetch_tile(smb, b, 0);
    CP_COMMIT();
    {
        int r = tid >> 1, hf = tid & 1;
        const float* qrow = qkv + ((size_t)(b * NTOK + q0 + r)) * ROWSTRIDE + hf * 96;
        uint32_t* qdst = sQH + r * LDH;
        float s = 0.f;
        #pragma unroll
        for (int i = 0; i < 24; i++) {
            float4 v = *(const float4*)(qrow + i * 4);
            int p0 = hf * 48 + 2 * i, p1 = p0 + 1;
            qdst[(p0 & 3) * 28 + (p0 >> 2)] = pack2q(v.x, v.y, s);
            qdst[(p1 & 3) * 28 + (p1 >> 2)] = pack2q(v.z, v.w, s);
        }
        s += __shfl_xor_sync(0xffffffffu, s, 1);
        if (hf == 0) sQ2[r] = s;
    }
    __syncthreads();

    const float q2a = sQ2[R + g];
    const float q2b = sQ2[R + 8 + g];

    float l0 = 0.f, l1 = 0.f;
    float o[24][4];
    #pragma unroll
    for (int n = 0; n < 24; n++) { o[n][0]=0.f; o[n][1]=0.f; o[n][2]=0.f; o[n][3]=0.f; }

    const uint32_t* qloPtr = sQH + (R + g) * LDH + t4 * 28;
    const uint32_t* qhiPtr = qloPtr + 8 * LDH;

    for (int st = 0; st < NTILES; ++st) {
        const int buf = st & 1;
        CP_WAIT0();
        __syncthreads();               // tile st converted data visible; (st-1) readers done

        if (st + 1 < NTILES) { prefetch_tile(smb, b, st + 1); CP_COMMIT(); }

        // ---- S = Q K^T (per warp: 16 rows x 64 keys), fp16 MMA ----
        const uint32_t* kPtr = sKH + buf * KH_SZ + g * LDH + t4 * 28;
        float sacc[8][4];
        #pragma unroll
        for (int n = 0; n < 8; n++) { sacc[n][0]=0.f; sacc[n][1]=0.f; sacc[n][2]=0.f; sacc[n][3]=0.f; }

        #pragma unroll
        for (int i = 0; i < 6; i++) {
            uint4 ql = *(const uint4*)(qloPtr + 4 * i);
            uint4 qh = *(const uint4*)(qhiPtr + 4 * i);
            #pragma unroll
            for (int n = 0; n < 8; n++) {
                uint4 kb = *(const uint4*)(kPtr + n * (8 * LDH) + 4 * i);
                mma16_f16(sacc[n], ql.x, qh.x, ql.y, qh.y, kb.x, kb.y);
                mma16_f16(sacc[n], ql.z, qh.z, ql.w, qh.w, kb.z, kb.w);
            }
        }

        // ---- softmax + fp16 PV per 16-key group ----
        const float* k2b = sK2 + buf * 64;
        #pragma unroll
        for (int t = 0; t < 4; t++) {
            float pr[2][4];
            #pragma unroll
            for (int u = 0; u < 2; u++) {
                const int n = 2 * t + u;
                float2 k2v = *(const float2*)(k2b + n * 8 + 2 * t4);
                float d0 = fmaxf(fmaf(sacc[n][0], -2.f, q2a + k2v.x), 0.f);
                float d1 = fmaxf(fmaf(sacc[n][1], -2.f, q2a + k2v.y), 0.f);
                float d2 = fmaxf(fmaf(sacc[n][2], -2.f, q2b + k2v.x), 0.f);
                float d3 = fmaxf(fmaf(sacc[n][3], -2.f, q2b + k2v.y), 0.f);
                pr[u][0] = ex2_approx(sqrt_approx(d0) * NEG_SCALE_LOG2E);
                pr[u][1] = ex2_approx(sqrt_approx(d1) * NEG_SCALE_LOG2E);
                pr[u][2] = ex2_approx(sqrt_approx(d2) * NEG_SCALE_LOG2E);
                pr[u][3] = ex2_approx(sqrt_approx(d3) * NEG_SCALE_LOG2E);
                l0 += pr[u][0] + pr[u][1];
                l1 += pr[u][2] + pr[u][3];
            }
            uint32_t pa0 = pack_f16(pr[0][0], pr[0][1]);
            uint32_t pa1 = pack_f16(pr[0][2], pr[0][3]);
            uint32_t pa2 = pack_f16(pr[1][0], pr[1][1]);
            uint32_t pa3 = pack_f16(pr[1][2], pr[1][3]);

            const uint32_t* vb0 = sVB + buf * VB_SZ + (8 * t + t4)     * LDV2 + g * 48;
            const uint32_t* vb1 = sVB + buf * VB_SZ + (8 * t + 4 + t4) * LDV2 + g * 48;
            #pragma unroll
            for (int m = 0; m < 6; m++) {
                uint4 w0 = *(const uint4*)(vb0 + 4 * m);
                uint4 w1 = *(const uint4*)(vb1 + 4 * m);
                mma16_f16(o[4*m+0], pa0, pa1, pa2, pa3, w0.x, w1.x);
                mma16_f16(o[4*m+1], pa0, pa1, pa2, pa3, w0.y, w1.y);
                mma16_f16(o[4*m+2], pa0, pa1, pa2, pa3, w0.z, w1.z);
                mma16_f16(o[4*m+3], pa0, pa1, pa2, pa3, w0.w, w1.w);
            }
        }
    }

    // ---- epilogue ----
    l0 += __shfl_xor_sync(0xffffffffu, l0, 1);
    l0 += __shfl_xor_sync(0xffffffffu, l0, 2);
    l1 += __shfl_xor_sync(0xffffffffu, l1, 1);
    l1 += __shfl_xor_sync(0xffffffffu, l1, 2);
    float il0 = 1.f / l0, il1 = 1.f / l1;
    size_t orow0 = ((size_t)(b * NTOK + q0 + R + g)) * DIMC;
    size_t orow1 = orow0 + (size_t)8 * DIMC;
    #pragma unroll
    for (int nn = 0; nn < 24; nn++) {
        int col = nn * 8 + 2 * t4;
        *(float2*)(out + orow0 + col) = make_float2(o[nn][0] * il0, o[nn][1] * il0);
        *(float2*)(out + orow1 + col) = make_float2(o[nn][2] * il1, o[nn][3] * il1);
    }
}

extern "C" void kernel_launch(void* const* d_in, const int* in_sizes, int n_in,
                              void* d_out, int out_size) {
    const float* qkv = (const float*)d_in[0];
    float* out = (float*)d_out;
    prepass_kernel<<<dim3(NTOK / 64, NB), 256>>>(qkv);
    cudaFuncSetAttribute(qkv_l2attn_kernel,
                         cudaFuncAttributeMaxDynamicSharedMemorySize, SMEM_BYTES);
    dim3 grid(NTOK / BR, NB);
    qkv_l2attn_kernel<<<grid, NTHREADS, SMEM_BYTES>>>(qkv, out);
}

// round 13
// speedup vs baseline: 2.3777x; 1.0059x over previous
#include <cuda_runtime.h>
#include <cuda_fp16.h>
#include <cstdint>
#include <cstddef>

#define DIMC 192
#define ROWSTRIDE 576
#define NB   8
#define NTOK 4096
#define BR   128
#define BC   64
#define NTILES (NTOK / BC)
#define NTHREADS 256
#define NEG_SCALE_LOG2E (-0.104117549f)   /* -(192^-0.5)*log2(e) */

#define LDH   112      /* K/Q fp16x2 row stride (u32); slot(p) = (p&3)*28 + (p>>2) */
#define LDV2  388      /* smem V row stride (u32); 388 % 32 == 4 -> conflict-free PV LDS.128 */
#define VROW  192      /* gmem vhalf compact row (u32) */

// ---- smem layout (u32 units) ----
#define QH_OFF  0
#define QH_SZ   (BR * LDH)          /* 14336 */
#define KH_OFF  (QH_OFF + QH_SZ)
#define KH_SZ   (BC * LDH)          /* 7168 x2 */
#define VB_OFF  (KH_OFF + 2 * KH_SZ)
#define VB_SZ   (32 * LDV2)         /* 12416 x2 */
#define K2_OFF  (VB_OFF + 2 * VB_SZ)   /* 2 x 64 */
#define Q2_OFF  (K2_OFF + 128)         /* 128 */
#define SMEM_U32 (Q2_OFF + 128)
#define SMEM_BYTES (SMEM_U32 * 4)      /* 215,040 B */

// ---- device scratch (converted operands; written by prepass) ----
__device__ uint32_t g_khalf[(size_t)NB * NTOK * LDH];
__device__ uint32_t g_vhalf[(size_t)NB * (NTOK / 2) * VROW];
__device__ float    g_k2[NB * NTOK];

__device__ __forceinline__ float sqrt_approx(float x) {
    float r; asm("sqrt.approx.f32 %0, %1;" : "=f"(r) : "f"(x)); return r;
}
__device__ __forceinline__ uint32_t pack_f16(float lo, float hi) {
    uint32_t d;
    asm("cvt.rn.f16x2.f32 %0, %1, %2;" : "=r"(d) : "f"(hi), "f"(lo));
    return d;
}
__device__ __forceinline__ uint32_t h2ex2(uint32_t a) {
    uint32_t d; asm("ex2.approx.f16x2 %0, %1;" : "=r"(d) : "r"(a)); return d;
}
__device__ __forceinline__ uint32_t hadd2u(uint32_t a, uint32_t b) {
    uint32_t d; asm("add.rn.f16x2 %0, %1, %2;" : "=r"(d) : "r"(a), "r"(b)); return d;
}
// pack and accumulate sum of squares of the ROUNDED values
__device__ __forceinline__ uint32_t pack2q(float lo, float hi, float& sq) {
    uint32_t u = pack_f16(lo, hi);
    __half2 h = *reinterpret_cast<__half2*>(&u);
    float2 f = __half22float2(h);
    sq += f.x * f.x + f.y * f.y;
    return u;
}
__device__ __forceinline__ uint32_t smem_u32p(const void* p) {
    uint32_t a;
    asm("{ .reg .u64 t; cvta.to.shared.u64 t, %1; cvt.u32.u64 %0, t; }" : "=r"(a) : "l"(p));
    return a;
}

#define CP_ASYNC16(dst, src) \
    asm volatile("cp.async.cg.shared.global [%0], [%1], 16;" :: "r"(dst), "l"(src) : "memory")
#define CP_COMMIT() asm volatile("cp.async.commit_group;" ::: "memory")
#define CP_WAIT0()  asm volatile("cp.async.wait_group 0;" ::: "memory")

__device__ __forceinline__ void mma16_f16(float* c,
        uint32_t a0, uint32_t a1, uint32_t a2, uint32_t a3,
        uint32_t b0, uint32_t b1) {
    asm volatile("mma.sync.aligned.m16n8k16.row.col.f32.f16.f16.f32 "
        "{%0,%1,%2,%3}, {%4,%5,%6,%7}, {%8,%9}, {%0,%1,%2,%3};"
        : "+f"(c[0]), "+f"(c[1]), "+f"(c[2]), "+f"(c[3])
        : "r"(a0), "r"(a1), "r"(a2), "r"(a3), "r"(b0), "r"(b1));
}

// ============ prepass: convert K/V to fp16 pair layouts + k2 ============
__global__ void __launch_bounds__(256)
prepass_kernel(const float* __restrict__ qkv)
{
    const int b   = blockIdx.y;
    const int t0  = blockIdx.x * 64;
    const int tid = threadIdx.x;

    {   // K: 4 threads per row; pre-permuted fp16x2 + k2 (rounded)
        int r = tid >> 2, q4 = tid & 3;
        int t = t0 + r;
        const float* krow = qkv + ((size_t)(b * NTOK + t)) * ROWSTRIDE + DIMC + q4 * 48;
        uint32_t* kdst = g_khalf + ((size_t)(b * NTOK + t)) * LDH;
        float s = 0.f;
        #pragma unroll
        for (int i = 0; i < 12; i++) {
            float4 v = *(const float4*)(krow + i * 4);
            int p0 = q4 * 24 + 2 * i, p1 = p0 + 1;
            kdst[(p0 & 3) * 28 + (p0 >> 2)] = pack2q(v.x, v.y, s);
            kdst[(p1 & 3) * 28 + (p1 >> 2)] = pack2q(v.z, v.w, s);
        }
        s += __shfl_xor_sync(0xffffffffu, s, 1);
        s += __shfl_xor_sync(0xffffffffu, s, 2);
        if (q4 == 0) g_k2[b * NTOK + t] = s;
    }
    {   // V: 8 threads per key pair; key-pair fp16x2 in slot24 layout
        int kp = tid >> 3, u8 = tid & 7;
        int tkey = t0 + 2 * kp;
        const float* ve = qkv + ((size_t)(b * NTOK + tkey)) * ROWSTRIDE + 2 * DIMC + u8 * 24;
        const float* vo = ve + ROWSTRIDE;
        uint32_t* vdst = g_vhalf + ((size_t)(b * (NTOK / 2) + (t0 >> 1) + kp)) * VROW;
        #pragma unroll
        for (int i = 0; i < 6; i++) {
            float4 a = *(const float4*)(ve + i * 4);
            float4 c4 = *(const float4*)(vo + i * 4);
            int c = u8 * 24 + i * 4;
            int blk = c & 7, rr = c >> 3;
            vdst[(blk + 0) * 24 + rr] = pack_f16(a.x, c4.x);
            vdst[(blk + 1) * 24 + rr] = pack_f16(a.y, c4.y);
            vdst[(blk + 2) * 24 + rr] = pack_f16(a.z, c4.z);
            vdst[(blk + 3) * 24 + rr] = pack_f16(a.w, c4.w);
        }
    }
}

// prefetch converted K/V/k2 for tile st; V offsets hoisted by caller
__device__ __forceinline__ void prefetch_tile(uint32_t smb, int b, int st,
                                              const int* vso, const int* vdo6) {
    const int tid = threadIdx.x;
    const int buf = st & 1;
    // K: tile is contiguous in gmem (64 rows x LDH) -> pure affine addressing
    const uint32_t* ksrc = g_khalf + ((size_t)(b * NTOK + st * BC)) * LDH;
    const uint32_t  kdst = smb + (KH_OFF + buf * KH_SZ) * 4;
    #pragma unroll
    for (int i = 0; i < 7; i++) {
        int cid = (tid + i * NTHREADS) * 4;   // 1792 chunks
        CP_ASYNC16(kdst + (uint32_t)cid * 4, ksrc + cid);
    }
    const uint32_t* vsrc = g_vhalf + ((size_t)(b * (NTOK / 2) + st * 32)) * VROW;
    const uint32_t  vdst = smb + (VB_OFF + buf * VB_SZ) * 4;
    #pragma unroll
    for (int i = 0; i < 6; i++) {
        CP_ASYNC16(vdst + (uint32_t)vdo6[i] * 4, vsrc + vso[i]);
    }
    if (tid < 16) {
        CP_ASYNC16(smb + (K2_OFF + buf * 64 + tid * 4) * 4,
                   g_k2 + b * NTOK + st * BC + tid * 4);
    }
}

__global__ void __launch_bounds__(NTHREADS, 1)
qkv_l2attn_kernel(const float* __restrict__ qkv, float* __restrict__ out)
{
    extern __shared__ uint32_t smu[];
    uint32_t* sQH = smu + QH_OFF;
    uint32_t* sKH = smu + KH_OFF;
    uint32_t* sVB = smu + VB_OFF;
    float*    sK2 = (float*)(smu + K2_OFF);
    float*    sQ2 = (float*)(smu + Q2_OFF);
    const uint32_t smb = smem_u32p(smu);

    const int tid  = threadIdx.x;
    const int warp = tid >> 5;
    const int lane = tid & 31;
    const int g    = lane >> 2;
    const int t4   = lane & 3;
    const int R    = warp * 16;

    const int b  = blockIdx.y;
    const int q0 = blockIdx.x * BR;

    // hoisted V chunk offsets (tile-invariant per thread)
    int vso[6], vdo6[6];
    #pragma unroll
    for (int i = 0; i < 6; i++) {
        int cid = tid + i * NTHREADS;
        int kp = cid / 48, j = cid - kp * 48;
        int jq = j / 6, jr = j - jq * 6;
        vso[i]  = kp * VROW + j * 4;
        vdo6[i] = kp * LDV2 + jq * 48 + jr * 4;
    }

    // ---- prologue: prefetch tile 0 + pack Q (fp16 permuted) + q2 (rounded) ----
    prefetch_tile(smb, b, 0, vso, vdo6);
    CP_COMMIT();
    {
        int r = tid >> 1, hf = tid & 1;
        const float* qrow = qkv + ((size_t)(b * NTOK + q0 + r)) * ROWSTRIDE + hf * 96;
        uint32_t* qdst = sQH + r * LDH;
        float s = 0.f;
        #pragma unroll
        for (int i = 0; i < 24; i++) {
            float4 v = *(const float4*)(qrow + i * 4);
            int p0 = hf * 48 + 2 * i, p1 = p0 + 1;
            qdst[(p0 & 3) * 28 + (p0 >> 2)] = pack2q(v.x, v.y, s);
            qdst[(p1 & 3) * 28 + (p1 >> 2)] = pack2q(v.z, v.w, s);
        }
        s += __shfl_xor_sync(0xffffffffu, s, 1);
        if (hf == 0) sQ2[r] = s;
    }
    __syncthreads();

    const float q2a = sQ2[R + g];
    const float q2b = sQ2[R + 8 + g];

    float l0 = 0.f, l1 = 0.f;
    float o[24][4];
    #pragma unroll
    for (int n = 0; n < 24; n++) { o[n][0]=0.f; o[n][1]=0.f; o[n][2]=0.f; o[n][3]=0.f; }

    const uint32_t* qloPtr = sQH + (R + g) * LDH + t4 * 28;
    const uint32_t* qhiPtr = qloPtr + 8 * LDH;

    for (int st = 0; st < NTILES; ++st) {
        const int buf = st & 1;
        CP_WAIT0();
        __syncthreads();               // tile st converted data visible; (st-1) readers done

        if (st + 1 < NTILES) { prefetch_tile(smb, b, st + 1, vso, vdo6); CP_COMMIT(); }

        // ---- S = Q K^T (per warp: 16 rows x 64 keys), fp16 MMA ----
        const uint32_t* kPtr = sKH + buf * KH_SZ + g * LDH + t4 * 28;
        float sacc[8][4];
        #pragma unroll
        for (int n = 0; n < 8; n++) { sacc[n][0]=0.f; sacc[n][1]=0.f; sacc[n][2]=0.f; sacc[n][3]=0.f; }

        #pragma unroll
        for (int i = 0; i < 6; i++) {
            uint4 ql = *(const uint4*)(qloPtr + 4 * i);
            uint4 qh = *(const uint4*)(qhiPtr + 4 * i);
            #pragma unroll
            for (int n = 0; n < 8; n++) {
                uint4 kb = *(const uint4*)(kPtr + n * (8 * LDH) + 4 * i);
                mma16_f16(sacc[n], ql.x, qh.x, ql.y, qh.y, kb.x, kb.y);
                mma16_f16(sacc[n], ql.z, qh.z, ql.w, qh.w, kb.z, kb.w);
            }
        }

        // ---- softmax (f16x2 exp) + fp16 PV per 16-key group ----
        const float* k2b = sK2 + buf * 64;
        uint32_t lacc0 = 0, lacc1 = 0;     // f16x2 partial sums (<=16 per half)
        #pragma unroll
        for (int t = 0; t < 4; t++) {
            float arg[2][4];
            #pragma unroll
            for (int u = 0; u < 2; u++) {
                const int n = 2 * t + u;
                float2 k2v = *(const float2*)(k2b + n * 8 + 2 * t4);
                float d0 = fmaxf(fmaf(sacc[n][0], -2.f, q2a + k2v.x), 0.f);
                float d1 = fmaxf(fmaf(sacc[n][1], -2.f, q2a + k2v.y), 0.f);
                float d2 = fmaxf(fmaf(sacc[n][2], -2.f, q2b + k2v.x), 0.f);
                float d3 = fmaxf(fmaf(sacc[n][3], -2.f, q2b + k2v.y), 0.f);
                arg[u][0] = sqrt_approx(d0) * NEG_SCALE_LOG2E;
                arg[u][1] = sqrt_approx(d1) * NEG_SCALE_LOG2E;
                arg[u][2] = sqrt_approx(d2) * NEG_SCALE_LOG2E;
                arg[u][3] = sqrt_approx(d3) * NEG_SCALE_LOG2E;
            }
            uint32_t pa0 = h2ex2(pack_f16(arg[0][0], arg[0][1]));   // row g
            uint32_t pa1 = h2ex2(pack_f16(arg[0][2], arg[0][3]));   // row g+8
            uint32_t pa2 = h2ex2(pack_f16(arg[1][0], arg[1][1]));   // row g
            uint32_t pa3 = h2ex2(pack_f16(arg[1][2], arg[1][3]));   // row g+8
            lacc0 = hadd2u(lacc0, hadd2u(pa0, pa2));
            lacc1 = hadd2u(lacc1, hadd2u(pa1, pa3));

            const uint32_t* vb0 = sVB + buf * VB_SZ + (8 * t + t4)     * LDV2 + g * 48;
            const uint32_t* vb1 = sVB + buf * VB_SZ + (8 * t + 4 + t4) * LDV2 + g * 48;
            #pragma unroll
            for (int m = 0; m < 6; m++) {
                uint4 w0 = *(const uint4*)(vb0 + 4 * m);
                uint4 w1 = *(const uint4*)(vb1 + 4 * m);
                mma16_f16(o[4*m+0], pa0, pa1, pa2, pa3, w0.x, w1.x);
                mma16_f16(o[4*m+1], pa0, pa1, pa2, pa3, w0.y, w1.y);
                mma16_f16(o[4*m+2], pa0, pa1, pa2, pa3, w0.z, w1.z);
                mma16_f16(o[4*m+3], pa0, pa1, pa2, pa3, w0.w, w1.w);
            }
        }
        {   // fold f16x2 tile sums into f32 accumulators
            float2 f0 = __half22float2(*reinterpret_cast<__half2*>(&lacc0));
            float2 f1 = __half22float2(*reinterpret_cast<__half2*>(&lacc1));
            l0 += f0.x + f0.y;
            l1 += f1.x + f1.y;
        }
    }

    // ---- epilogue ----
    l0 += __shfl_xor_sync(0xffffffffu, l0, 1);
    l0 += __shfl_xor_sync(0xffffffffu, l0, 2);
    l1 += __shfl_xor_sync(0xffffffffu, l1, 1);
    l1 += __shfl_xor_sync(0xffffffffu, l1, 2);
    float il0 = 1.f / l0, il1 = 1.f / l1;
    size_t orow0 = ((size_t)(b * NTOK + q0 + R + g)) * DIMC;
    size_t orow1 = orow0 + (size_t)8 * DIMC;
    #pragma unroll
    for (int nn = 0; nn < 24; nn++) {
        int col = nn * 8 + 2 * t4;
        *(float2*)(out + orow0 + col) = make_float2(o[nn][0] * il0, o[nn][1] * il0);
        *(float2*)(out + orow1 + col) = make_float2(o[nn][2] * il1, o[nn][3] * il1);
    }
}

extern "C" void kernel_launch(void* const* d_in, const int* in_sizes, int n_in,
                              void* d_out, int out_size) {
    const float* qkv = (const float*)d_in[0];
    float* out = (float*)d_out;
    prepass_kernel<<<dim3(NTOK / 64, NB), 256>>>(qkv);
    cudaFuncSetAttribute(qkv_l2attn_kernel,
                         cudaFuncAttributeMaxDynamicSharedMemorySize, SMEM_BYTES);
    dim3 grid(NTOK / BR, NB);
    qkv_l2attn_kernel<<<grid, NTHREADS, SMEM_BYTES>>>(qkv, out);
}

// round 15
// speedup vs baseline: 2.7482x; 1.1558x over previous
#include <cuda_runtime.h>
#include <cuda_fp16.h>
#include <cstdint>
#include <cstddef>

#define DIMC 192
#define ROWSTRIDE 576
#define NB   8
#define NTOK 4096
#define BR   128
#define BC   64
#define NTILES (NTOK / BC)
#define NTHREADS 256
#define CS 0.10411755f            /* (192^-0.5) * log2(e) : folded into packed Q/K */

#define LDH   112      /* K fp16x2 row stride (u32); slot(p) = (p&3)*28 + (p>>2) */
#define LDQP  208      /* Q row-pair stride (u32); uint4 = complete HMMA A fragment */
#define LDVP  388      /* V row stride (u32, padded); uint4 = B pairs for 2 MMAs */
#define VTILE 6208     /* 16 * LDVP : one V tile (padded layout, stored in gmem) */

// ---- smem layout (u32 units) ----
#define QH_OFF  0
#define QH_SZ   (8 * 8 * LDQP)      /* 13312 */
#define KH_OFF  (QH_OFF + QH_SZ)
#define KH_SZ   (BC * LDH)          /* 7168 x2 */
#define VB_OFF  (KH_OFF + 2 * KH_SZ)
#define VB_SZ   VTILE               /* 6208 x2 */
#define K2_OFF  (VB_OFF + 2 * VB_SZ)   /* 2 x 64 */
#define Q2_OFF  (K2_OFF + 128)         /* 128 */
#define SMEM_U32 (Q2_OFF + 128)
#define SMEM_BYTES (SMEM_U32 * 4)      /* 161,280 B */

// ---- device scratch (converted operands; written by prepass) ----
__device__ uint32_t g_khalf[(size_t)NB * NTOK * LDH];
__device__ uint32_t g_vhalf[(size_t)NB * NTILES * VTILE];
__device__ float    g_k2[NB * NTOK];

__device__ __forceinline__ float sqrt_approx(float x) {
    float r; asm("sqrt.approx.f32 %0, %1;" : "=f"(r) : "f"(x)); return r;
}
__device__ __forceinline__ uint32_t pack_f16(float lo, float hi) {
    uint32_t d;
    asm("cvt.rn.f16x2.f32 %0, %1, %2;" : "=r"(d) : "f"(hi), "f"(lo));
    return d;
}
__device__ __forceinline__ uint32_t h2ex2(uint32_t a) {
    uint32_t d; asm("ex2.approx.f16x2 %0, %1;" : "=r"(d) : "r"(a)); return d;
}
__device__ __forceinline__ uint32_t hadd2u(uint32_t a, uint32_t b) {
    uint32_t d; asm("add.rn.f16x2 %0, %1, %2;" : "=r"(d) : "r"(a), "r"(b)); return d;
}
// pack (scale applied by caller) and accumulate sum-of-squares of ROUNDED values
__device__ __forceinline__ uint32_t pack2q(float lo, float hi, float& sq) {
    uint32_t u = pack_f16(lo, hi);
    __half2 h = *reinterpret_cast<__half2*>(&u);
    float2 f = __half22float2(h);
    sq += f.x * f.x + f.y * f.y;
    return u;
}
__device__ __forceinline__ uint32_t smem_u32p(const void* p) {
    uint32_t a;
    asm("{ .reg .u64 t; cvta.to.shared.u64 t, %1; cvt.u32.u64 %0, t; }" : "=r"(a) : "l"(p));
    return a;
}

#define CP_ASYNC16(dst, src) \
    asm volatile("cp.async.cg.shared.global [%0], [%1], 16;" :: "r"(dst), "l"(src) : "memory")
#define CP_COMMIT() asm volatile("cp.async.commit_group;" ::: "memory")
#define CP_WAIT0()  asm volatile("cp.async.wait_group 0;" ::: "memory")

__device__ __forceinline__ void mma16_f16(float* c,
        uint32_t a0, uint32_t a1, uint32_t a2, uint32_t a3,
        uint32_t b0, uint32_t b1) {
    asm volatile("mma.sync.aligned.m16n8k16.row.col.f32.f16.f16.f32 "
        "{%0,%1,%2,%3}, {%4,%5,%6,%7}, {%8,%9}, {%0,%1,%2,%3};"
        : "+f"(c[0]), "+f"(c[1]), "+f"(c[2]), "+f"(c[3])
        : "r"(a0), "r"(a1), "r"(a2), "r"(a3), "r"(b0), "r"(b1));
}

// ============ prepass: K (scaled, pair-permuted) + V (MMA-pair layout) + k2 ============
__global__ void __launch_bounds__(256)
prepass_kernel(const float* __restrict__ qkv)
{
    __shared__ float Vs[64 * 192];
    const int b   = blockIdx.y;
    const int st  = blockIdx.x;
    const int t0  = st * 64;
    const int tid = threadIdx.x;

    // stage V tile (f32, coalesced)
    #pragma unroll
    for (int i = 0; i < 12; i++) {
        int idx = tid + i * 256;            // 3072 = 64 rows x 48 float4
        int r = idx / 48, c = (idx - r * 48) * 4;
        *(float4*)(Vs + r * 192 + c) =
            *(const float4*)(qkv + ((size_t)(b * NTOK + t0 + r)) * ROWSTRIDE + 2 * DIMC + c);
    }

    // K: 4 threads per row; scaled pack + k2 (from rounded values)
    {
        int r = tid >> 2, q4 = tid & 3;
        int t = t0 + r;
        const float* krow = qkv + ((size_t)(b * NTOK + t)) * ROWSTRIDE + DIMC + q4 * 48;
        uint32_t* kdst = g_khalf + ((size_t)(b * NTOK + t)) * LDH;
        float s = 0.f;
        #pragma unroll
        for (int i = 0; i < 12; i++) {
            float4 v = *(const float4*)(krow + i * 4);
            int p0 = q4 * 24 + 2 * i, p1 = p0 + 1;
            kdst[(p0 & 3) * 28 + (p0 >> 2)] = pack2q(v.x * CS, v.y * CS, s);
            kdst[(p1 & 3) * 28 + (p1 >> 2)] = pack2q(v.z * CS, v.w * CS, s);
        }
        s += __shfl_xor_sync(0xffffffffu, s, 1);
        s += __shfl_xor_sync(0xffffffffu, s, 2);
        if (q4 == 0) g_k2[b * NTOK + t] = s;
    }
    __syncthreads();

    // V: write MMA-pair layout, fully coalesced uint4 chunks
    uint32_t* vout = g_vhalf + ((size_t)(b * NTILES + st)) * VTILE;
    #pragma unroll
    for (int i = 0; i < 7; i++) {
        int c = tid + i * 256;              // 1552 chunks (16 rows x 97 uint4)
        if (i == 6 && c >= 1552) break;
        int rr = c / 97, k4 = c - rr * 97;
        uint4 w = make_uint4(0u, 0u, 0u, 0u);
        if (k4 < 96) {
            int t = rr >> 2, t4 = rr & 3;
            uint32_t vals[4];
            #pragma unroll
            for (int jj = 0; jj < 4; jj++) {
                int k = k4 * 4 + jj;
                int gg = k / 48;
                int rem = k - gg * 48;
                int m = rem >> 1, h = rem & 1;
                int col = 8 * m + gg;
                int key = 16 * t + 8 * h + 2 * t4;
                vals[jj] = pack_f16(Vs[key * 192 + col], Vs[(key + 1) * 192 + col]);
            }
            w = make_uint4(vals[0], vals[1], vals[2], vals[3]);
        }
        *(uint4*)(vout + (size_t)rr * LDVP + k4 * 4) = w;
    }
}

// prefetch converted K/V/k2 for tile st into buffer (st & 1): fully affine
__device__ __forceinline__ void prefetch_tile(uint32_t smb, int b, int st) {
    const int tid = threadIdx.x;
    const int buf = st & 1;
    const uint32_t* ksrc = g_khalf + ((size_t)(b * NTOK + st * BC)) * LDH;
    const uint32_t  kdst = smb + (KH_OFF + buf * KH_SZ) * 4;
    #pragma unroll
    for (int i = 0; i < 7; i++) {           // 1792 uint4
        int cid = (tid + i * NTHREADS) * 4;
        CP_ASYNC16(kdst + (uint32_t)cid * 4, ksrc + cid);
    }
    const uint32_t* vsrc = g_vhalf + ((size_t)(b * NTILES + st)) * VTILE;
    const uint32_t  vdst = smb + (VB_OFF + buf * VB_SZ) * 4;
    #pragma unroll
    for (int i = 0; i < 6; i++) {           // 1536 uint4
        int cid = (tid + i * NTHREADS) * 4;
        CP_ASYNC16(vdst + (uint32_t)cid * 4, vsrc + cid);
    }
    if (tid < 16) {                          // remaining 16 V chunks
        int cid = (1536 + tid) * 4;
        CP_ASYNC16(vdst + (uint32_t)cid * 4, vsrc + cid);
    }
    if (tid < 16) {
        CP_ASYNC16(smb + (K2_OFF + buf * 64 + tid * 4) * 4,
                   g_k2 + b * NTOK + st * BC + tid * 4);
    }
}

__global__ void __launch_bounds__(NTHREADS, 1)
qkv_l2attn_kernel(const float* __restrict__ qkv, float* __restrict__ out)
{
    extern __shared__ uint32_t smu[];
    uint32_t* sQH = smu + QH_OFF;
    uint32_t* sKH = smu + KH_OFF;
    uint32_t* sVB = smu + VB_OFF;
    float*    sK2 = (float*)(smu + K2_OFF);
    float*    sQ2 = (float*)(smu + Q2_OFF);
    const uint32_t smb = smem_u32p(smu);

    const int tid  = threadIdx.x;
    const int warp = tid >> 5;
    const int lane = tid & 31;
    const int g    = lane >> 2;
    const int t4   = lane & 3;
    const int R    = warp * 16;

    const int b  = blockIdx.y;
    const int q0 = blockIdx.x * BR;

    // ---- prologue: prefetch tile 0; pack Q into A-fragment-native layout + q2 ----
    prefetch_tile(smb, b, 0);
    CP_COMMIT();
    {
        // 4 threads (q=0..3) per row-pair rp; EACH writes 48 of the 192 slots.
        int wb = tid >> 5, rp = (tid >> 2) & 7, q = tid & 3;
        const float* qrow0 = qkv + ((size_t)(b * NTOK + q0 + wb * 16 + rp)) * ROWSTRIDE;
        const float* qrow1 = qrow0 + (size_t)8 * ROWSTRIDE;
        uint32_t* qdst = sQH + wb * (8 * LDQP) + rp * LDQP;
        float slo = 0.f, shi = 0.f;
        #pragma unroll
        for (int si = 0; si < 48; si++) {
            int s = q * 48 + si;                     // slot 0..191
            int kb = s >> 4, r16 = s & 15, t4s = r16 >> 2, j = r16 & 3;
            int p = kb * 8 + t4s + ((j >> 1) << 2);  // f16x2 pair index in row
            const float* src = ((j & 1) ? qrow1 : qrow0) + 2 * p;
            float2 v = *(const float2*)src;
            if (j & 1) qdst[s] = pack2q(v.x * CS, v.y * CS, shi);
            else       qdst[s] = pack2q(v.x * CS, v.y * CS, slo);
        }
        slo += __shfl_xor_sync(0xffffffffu, slo, 1);
        slo += __shfl_xor_sync(0xffffffffu, slo, 2);
        shi += __shfl_xor_sync(0xffffffffu, shi, 1);
        shi += __shfl_xor_sync(0xffffffffu, shi, 2);
        if (q == 0) {
            sQ2[wb * 16 + rp]     = slo;
            sQ2[wb * 16 + rp + 8] = shi;
        }
    }
    __syncthreads();

    const float q2a = sQ2[R + g];
    const float q2b = sQ2[R + 8 + g];

    float l0 = 0.f, l1 = 0.f;
    float o[24][4];
    #pragma unroll
    for (int n = 0; n < 24; n++) { o[n][0]=0.f; o[n][1]=0.f; o[n][2]=0.f; o[n][3]=0.f; }

    const uint32_t* qPtr  = sQH + warp * (8 * LDQP) + g * LDQP;
    const uint32_t* kPtr0 = sKH + g * LDH + t4 * 28;

    for (int st = 0; st < NTILES; ++st) {
        const int buf = st & 1;
        CP_WAIT0();
        __syncthreads();               // tile st data visible; (st-1) readers done

        if (st + 1 < NTILES) { prefetch_tile(smb, b, st + 1); CP_COMMIT(); }

        // ---- S = Q K^T (per warp: 16 rows x 64 keys); all operands MMA-native ----
        const uint32_t* kPtr = kPtr0 + buf * KH_SZ;
        float sacc[8][4];
        #pragma unroll
        for (int n = 0; n < 8; n++) { sacc[n][0]=0.f; sacc[n][1]=0.f; sacc[n][2]=0.f; sacc[n][3]=0.f; }

        #pragma unroll
        for (int i = 0; i < 6; i++) {
            uint4 qa = *(const uint4*)(qPtr + (2 * i) * 16 + 4 * t4);
            uint4 qb = *(const uint4*)(qPtr + (2 * i + 1) * 16 + 4 * t4);
            #pragma unroll
            for (int n = 0; n < 8; n++) {
                uint4 kb = *(const uint4*)(kPtr + n * (8 * LDH) + 4 * i);
                mma16_f16(sacc[n], qa.x, qa.y, qa.z, qa.w, kb.x, kb.y);
                mma16_f16(sacc[n], qb.x, qb.y, qb.z, qb.w, kb.z, kb.w);
            }
        }

        // ---- softmax (scale pre-folded; sign via XOR) + PV ----
        const float* k2b = sK2 + buf * 64;
        uint32_t lacc0 = 0, lacc1 = 0;
        #pragma unroll
        for (int t = 0; t < 4; t++) {
            float sa[2][4];
            #pragma unroll
            for (int u = 0; u < 2; u++) {
                const int n = 2 * t + u;
                float2 k2v = *(const float2*)(k2b + n * 8 + 2 * t4);
                float d0 = fmaxf(fmaf(sacc[n][0], -2.f, q2a + k2v.x), 0.f);
                float d1 = fmaxf(fmaf(sacc[n][1], -2.f, q2a + k2v.y), 0.f);
                float d2 = fmaxf(fmaf(sacc[n][2], -2.f, q2b + k2v.x), 0.f);
                float d3 = fmaxf(fmaf(sacc[n][3], -2.f, q2b + k2v.y), 0.f);
                sa[u][0] = sqrt_approx(d0);
                sa[u][1] = sqrt_approx(d1);
                sa[u][2] = sqrt_approx(d2);
                sa[u][3] = sqrt_approx(d3);
            }
            uint32_t pa0 = h2ex2(pack_f16(sa[0][0], sa[0][1]) ^ 0x80008000u);
            uint32_t pa1 = h2ex2(pack_f16(sa[0][2], sa[0][3]) ^ 0x80008000u);
            uint32_t pa2 = h2ex2(pack_f16(sa[1][0], sa[1][1]) ^ 0x80008000u);
            uint32_t pa3 = h2ex2(pack_f16(sa[1][2], sa[1][3]) ^ 0x80008000u);
            lacc0 = hadd2u(lacc0, hadd2u(pa0, pa2));
            lacc1 = hadd2u(lacc1, hadd2u(pa1, pa3));

            const uint32_t* vp = sVB + buf * VB_SZ + (t * 4 + t4) * LDVP + g * 48;
            #pragma unroll
            for (int j = 0; j < 12; j++) {
                uint4 w = *(const uint4*)(vp + 4 * j);
                mma16_f16(o[2*j],   pa0, pa1, pa2, pa3, w.x, w.y);
                mma16_f16(o[2*j+1], pa0, pa1, pa2, pa3, w.z, w.w);
            }
        }
        {   // fold f16x2 tile sums into f32 accumulators
            float2 f0 = __half22float2(*reinterpret_cast<__half2*>(&lacc0));
            float2 f1 = __half22float2(*reinterpret_cast<__half2*>(&lacc1));
            l0 += f0.x + f0.y;
            l1 += f1.x + f1.y;
        }
    }

    // ---- epilogue ----
    l0 += __shfl_xor_sync(0xffffffffu, l0, 1);
    l0 += __shfl_xor_sync(0xffffffffu, l0, 2);
    l1 += __shfl_xor_sync(0xffffffffu, l1, 1);
    l1 += __shfl_xor_sync(0xffffffffu, l1, 2);
    float il0 = 1.f / l0, il1 = 1.f / l1;
    size_t orow0 = ((size_t)(b * NTOK + q0 + R + g)) * DIMC;
    size_t orow1 = orow0 + (size_t)8 * DIMC;
    #pragma unroll
    for (int nn = 0; nn < 24; nn++) {
        int col = nn * 8 + 2 * t4;
        *(float2*)(out + orow0 + col) = make_float2(o[nn][0] * il0, o[nn][1] * il0);
        *(float2*)(out + orow1 + col) = make_float2(o[nn][2] * il1, o[nn][3] * il1);
    }
}

extern "C" void kernel_launch(void* const* d_in, const int* in_sizes, int n_in,
                              void* d_out, int out_size) {
    const float* qkv = (const float*)d_in[0];
    float* out = (float*)d_out;
    prepass_kernel<<<dim3(NTILES, NB), 256>>>(qkv);
    cudaFuncSetAttribute(qkv_l2attn_kernel,
                         cudaFuncAttributeMaxDynamicSharedMemorySize, SMEM_BYTES);
    dim3 grid(NTOK / BR, NB);
    qkv_l2attn_kernel<<<grid, NTHREADS, SMEM_BYTES>>>(qkv, out);
}